// round 13
// baseline (speedup 1.0000x reference)
#include <cuda_runtime.h>
#include <cuda_bf16.h>
#include <math.h>
#include <stdint.h>

#define NN   8192
#define DIN  512
#define DHID 256
#define DOUT 128
#define CAP  256
#define NEG  0.25f

// ---------------- scratch (device globals) ----------------------------------
__device__ float g_y1[NN * DHID];
__device__ float g_y2[NN * DHID];
__device__ float g_h [NN * DOUT];
__device__ float g_f1[NN];
__device__ float g_f2[NN];
__device__ int   g_cnt [NN];
__device__ int   g_ecol[NN * CAP];
__device__ float g_eval[NN * CAP];
__device__ float g_part[64 * DOUT];
__device__ float g_hmean[DOUT];

__device__ __nv_bfloat16 g_xh [NN * DIN],  g_xl [NN * DIN];
__device__ __nv_bfloat16 g_x1h[NN * DHID], g_x1l[NN * DHID];
__device__ __nv_bfloat16 g_x2h[NN * DHID], g_x2l[NN * DHID];
__device__ __nv_bfloat16 g_w1th[DHID * DIN],  g_w1tl[DHID * DIN];
__device__ __nv_bfloat16 g_w2th[DHID * DHID], g_w2tl[DHID * DHID];
__device__ __nv_bfloat16 g_wgth[DOUT * DHID], g_wgtl[DOUT * DHID];

__device__ __forceinline__ float leaky(float x) { return x >= 0.f ? x : NEG * x; }

__device__ __forceinline__ uint32_t smem_to_u32(const void* p) {
    uint32_t a;
    asm("{ .reg .u64 t; cvta.to.shared.u64 t, %1; cvt.u32.u64 %0, t; }" : "=r"(a) : "l"(p));
    return a;
}
__device__ __forceinline__ void ldsm_x4(uint32_t* r, uint32_t addr) {
    asm volatile("ldmatrix.sync.aligned.m8n8.x4.shared.b16 {%0,%1,%2,%3}, [%4];"
                 : "=r"(r[0]), "=r"(r[1]), "=r"(r[2]), "=r"(r[3]) : "r"(addr));
}
__device__ __forceinline__ void mma16816(float* c, const uint32_t* a, uint32_t b0, uint32_t b1) {
    asm volatile("mma.sync.aligned.m16n8k16.row.col.f32.bf16.bf16.f32 "
                 "{%0,%1,%2,%3}, {%4,%5,%6,%7}, {%8,%9}, {%0,%1,%2,%3};"
                 : "+f"(c[0]), "+f"(c[1]), "+f"(c[2]), "+f"(c[3])
                 : "r"(a[0]), "r"(a[1]), "r"(a[2]), "r"(a[3]), "r"(b0), "r"(b1));
}
__device__ __forceinline__ void cp16(uint32_t saddr, const void* g) {
    asm volatile("cp.async.ca.shared.global [%0], [%1], 16;" :: "r"(saddr), "l"(g));
}
#define CP_COMMIT() asm volatile("cp.async.commit_group;" ::: "memory")
#define CP_WAIT(n)  asm volatile("cp.async.wait_group %0;" :: "n"(n) : "memory")

// ---------------- 1) edge extraction: 256 blocks x 32 rows (co-resident) ------
__global__ void k_extract(const float* __restrict__ adj) {
    __shared__ float srow[NN];
    __shared__ int   scnt[256];
    const int tid = threadIdx.x;
    for (int rr = 0; rr < 32; rr++) {
        const int row = blockIdx.x * 32 + rr;
        const float4* arow4 = (const float4*)(adj + (size_t)row * NN);
        float4* srow4 = (float4*)srow;
        __syncthreads();   // previous row's reads done before overwrite
        for (int j = tid; j < NN / 4; j += 256) srow4[j] = arow4[j];
        __syncthreads();

        int c = 0;
#pragma unroll
        for (int i = 0; i < 32; i++) if (srow[i * 256 + tid] > 0.f) c++;
        scnt[tid] = c;
        __syncthreads();
        for (int off = 1; off < 256; off <<= 1) {
            int v = scnt[tid];
            if (tid >= off) v += scnt[tid - off];
            __syncthreads();
            scnt[tid] = v;
            __syncthreads();
        }
        const int my_off = scnt[tid] - c;
        if (tid == 0) {
            int total = scnt[255];
            g_cnt[row] = total < CAP ? total : CAP;
        }
        const int base = row * CAP;
        int k = 0;
#pragma unroll
        for (int i = 0; i < 32; i++) {
            float v = srow[i * 256 + tid];
            if (v > 0.f) {
                int p = my_off + k;
                if (p < CAP) { g_ecol[base + p] = i * 256 + tid; g_eval[base + p] = v; }
                k++;
            }
        }
    }
}

// ---------------- 2) fused prep: x split + W transposes -----------------------
__global__ void k_prep(const float* __restrict__ x,
                       const float* __restrict__ W1, const float* __restrict__ W2,
                       const float* __restrict__ Wg) {
    int b = blockIdx.x;
    if (b < 4096) {
        int i = b * 256 + threadIdx.x;
        float4 v = ((const float4*)x)[i];
        __nv_bfloat16 h0 = __float2bfloat16(v.x), h1 = __float2bfloat16(v.y);
        __nv_bfloat16 h2 = __float2bfloat16(v.z), h3 = __float2bfloat16(v.w);
        __nv_bfloat162* hp = (__nv_bfloat162*)g_xh;
        __nv_bfloat162* lp = (__nv_bfloat162*)g_xl;
        hp[2 * i]     = __nv_bfloat162(h0, h1);
        hp[2 * i + 1] = __nv_bfloat162(h2, h3);
        lp[2 * i]     = __nv_bfloat162(__float2bfloat16(v.x - __bfloat162float(h0)),
                                       __float2bfloat16(v.y - __bfloat162float(h1)));
        lp[2 * i + 1] = __nv_bfloat162(__float2bfloat16(v.z - __bfloat162float(h2)),
                                       __float2bfloat16(v.w - __bfloat162float(h3)));
        return;
    }
    b -= 4096;
    __shared__ float tile[32][33];
    const float* W; __nv_bfloat16 *th, *tl; int K, N, tk, tn;
    if (b < 128) {
        W = W1; th = g_w1th; tl = g_w1tl; K = DIN; N = DHID;
        tk = (b >> 3) * 32; tn = (b & 7) * 32;
    } else if (b < 192) {
        b -= 128; W = W2; th = g_w2th; tl = g_w2tl; K = DHID; N = DHID;
        tk = (b >> 3) * 32; tn = (b & 7) * 32;
    } else {
        b -= 192; W = Wg; th = g_wgth; tl = g_wgtl; K = DHID; N = DOUT;
        tk = (b >> 2) * 32; tn = (b & 3) * 32;
    }
    const int tx = threadIdx.x & 31, ty = threadIdx.x >> 5;
#pragma unroll
    for (int i = 0; i < 32; i += 8)
        tile[ty + i][tx] = W[(size_t)(tk + ty + i) * N + tn + tx];
    __syncthreads();
#pragma unroll
    for (int i = 0; i < 32; i += 8) {
        float v = tile[tx][ty + i];
        __nv_bfloat16 hb = __float2bfloat16(v);
        size_t o = (size_t)(tn + ty + i) * K + tk + tx;
        th[o] = hb;
        tl[o] = __float2bfloat16(v - __bfloat162float(hb));
    }
}

// ---------------- 3) 3-stage pipelined HMMA bf16-split GEMM ------------------
#define SPAD 40
template<int BM, int BN, int WM, int WN>
__global__ void __launch_bounds__(WM * WN * 32) k_hmma(
    const __nv_bfloat16* __restrict__ Ah, const __nv_bfloat16* __restrict__ Al,
    const __nv_bfloat16* __restrict__ Bh, const __nv_bfloat16* __restrict__ Bl,
    float* __restrict__ C, int N, int K)
{
    constexpr int T = WM * WN * 32;
    constexpr int ARR_A = BM * SPAD * 2;
    constexpr int ARR_BB = BN * SPAD * 2;
    constexpr int OFF_AH = 0;
    constexpr int OFF_AL = ARR_A;
    constexpr int OFF_BH = 2 * ARR_A;
    constexpr int OFF_BL = 2 * ARR_A + ARR_BB;
    constexpr int STAGE  = 2 * ARR_A + 2 * ARR_BB;

    extern __shared__ char dsm[];
    const uint32_t sb = smem_to_u32(dsm);
    const int tid = threadIdx.x, wid = tid >> 5, lane = tid & 31;
    const int m0 = blockIdx.x * BM, n0 = blockIdx.y * BN;
    const int wm = (wid % WM) * 32, wn = (wid / WM) * 32;

    float acc[2][4][4];
#pragma unroll
    for (int i = 0; i < 2; i++)
#pragma unroll
        for (int j = 0; j < 4; j++)
#pragma unroll
            for (int q = 0; q < 4; q++) acc[i][j][q] = 0.f;

    const int nch = K >> 5;

    auto issue = [&](int kc) {
        const uint32_t st = sb + (kc % 3) * STAGE;
#pragma unroll
        for (int idx = tid; idx < BM * 4; idx += T) {
            const int r = idx >> 2, c = idx & 3;
            const uint32_t so = (uint32_t)(r * SPAD + c * 8) * 2;
            const size_t gA = (size_t)(m0 + r) * K + kc * 32 + c * 8;
            cp16(st + OFF_AH + so, Ah + gA);
            cp16(st + OFF_AL + so, Al + gA);
        }
#pragma unroll
        for (int idx = tid; idx < BN * 4; idx += T) {
            const int r = idx >> 2, c = idx & 3;
            const uint32_t so = (uint32_t)(r * SPAD + c * 8) * 2;
            const size_t gB = (size_t)(n0 + r) * K + kc * 32 + c * 8;
            cp16(st + OFF_BH + so, Bh + gB);
            cp16(st + OFF_BL + so, Bl + gB);
        }
        CP_COMMIT();
    };

    issue(0);
    issue(1);

    for (int kc = 0; kc < nch; kc++) {
        if (kc + 1 < nch) { CP_WAIT(1); } else { CP_WAIT(0); }
        __syncthreads();
        if (kc + 2 < nch) issue(kc + 2);

        const uint32_t st = sb + (kc % 3) * STAGE;
#pragma unroll
        for (int ks = 0; ks < 2; ks++) {
            const int kb = ks * 16;
            const uint32_t aoff = ((wm + (lane & 15)) * SPAD + kb + 8 * (lane >> 4)) * 2;
            uint32_t afr[2][2][4];
            ldsm_x4(afr[0][0], st + OFF_AH + aoff);
            ldsm_x4(afr[0][1], st + OFF_AL + aoff);
            ldsm_x4(afr[1][0], st + OFF_AH + aoff + 16 * SPAD * 2);
            ldsm_x4(afr[1][1], st + OFF_AL + aoff + 16 * SPAD * 2);
            const uint32_t boff = ((wn + 8 * (lane >> 4) + (lane & 7)) * SPAD
                                   + kb + 8 * ((lane >> 3) & 1)) * 2;
            uint32_t bfr[2][2][4];
            ldsm_x4(bfr[0][0], st + OFF_BH + boff);
            ldsm_x4(bfr[0][1], st + OFF_BL + boff);
            ldsm_x4(bfr[1][0], st + OFF_BH + boff + 16 * SPAD * 2);
            ldsm_x4(bfr[1][1], st + OFF_BL + boff + 16 * SPAD * 2);

#pragma unroll
            for (int i = 0; i < 2; i++)
#pragma unroll
                for (int j = 0; j < 4; j++) {
                    const int p = j >> 1, s = (j & 1) * 2;
                    mma16816(acc[i][j], afr[i][0], bfr[p][0][s], bfr[p][0][s + 1]);
                    mma16816(acc[i][j], afr[i][0], bfr[p][1][s], bfr[p][1][s + 1]);
                    mma16816(acc[i][j], afr[i][1], bfr[p][0][s], bfr[p][0][s + 1]);
                }
        }
    }

    const int g = lane >> 2, t2 = (lane & 3) * 2;
#pragma unroll
    for (int i = 0; i < 2; i++)
#pragma unroll
        for (int j = 0; j < 4; j++) {
            const int rm = m0 + wm + 16 * i + g;
            const int cn = n0 + wn + 8 * j + t2;
            *(float2*)&C[(size_t)rm * N + cn]       = make_float2(acc[i][j][0], acc[i][j][1]);
            *(float2*)&C[(size_t)(rm + 8) * N + cn] = make_float2(acc[i][j][2], acc[i][j][3]);
        }
}

// ---------------- 4) warp-per-row SpMM (R10 form: reg-staged, shfl) -----------
__global__ void __launch_bounds__(256) k_spmm(
    const float* __restrict__ y, const float* __restrict__ bias,
    __nv_bfloat16* __restrict__ oh, __nv_bfloat16* __restrict__ ol) {
    const int row = blockIdx.x * 8 + (threadIdx.x >> 5);
    const int lane = threadIdx.x & 31;
    const int cnt = g_cnt[row];

    float ev[8]; int ec[8];
    const int base = row * CAP;
#pragma unroll
    for (int s = 0; s < 8; s++) {
        int t = lane + s * 32;
        if (t < cnt) { ec[s] = g_ecol[base + t]; ev[s] = g_eval[base + t]; }
        else         { ec[s] = 0;               ev[s] = 0.f; }
    }

    float4 acc0 = make_float4(0.f, 0.f, 0.f, 0.f);
    float4 acc1 = make_float4(0.f, 0.f, 0.f, 0.f);
    const int nslots = (cnt + 31) >> 5;
    for (int s = 0; s < nslots; s++) {
        const int lim = min(32, cnt - s * 32);
        for (int u = 0; u < lim; u++) {
            const float w = __shfl_sync(0xffffffffu, ev[s], u);
            const int   j = __shfl_sync(0xffffffffu, ec[s], u);
            const float4* yr = (const float4*)(y + (size_t)j * DHID);
            float4 v0 = yr[lane];
            float4 v1 = yr[lane + 32];
            acc0.x = fmaf(w, v0.x, acc0.x); acc0.y = fmaf(w, v0.y, acc0.y);
            acc0.z = fmaf(w, v0.z, acc0.z); acc0.w = fmaf(w, v0.w, acc0.w);
            acc1.x = fmaf(w, v1.x, acc1.x); acc1.y = fmaf(w, v1.y, acc1.y);
            acc1.z = fmaf(w, v1.z, acc1.z); acc1.w = fmaf(w, v1.w, acc1.w);
        }
    }
    const float4 b0 = ((const float4*)bias)[lane];
    const float4 b1 = ((const float4*)bias)[lane + 32];
    float r0[8] = { leaky(acc0.x + b0.x), leaky(acc0.y + b0.y),
                    leaky(acc0.z + b0.z), leaky(acc0.w + b0.w),
                    leaky(acc1.x + b1.x), leaky(acc1.y + b1.y),
                    leaky(acc1.z + b1.z), leaky(acc1.w + b1.w) };
    __nv_bfloat162 hv[4], lv[4];
#pragma unroll
    for (int q = 0; q < 4; q++) {
        int s0 = q * 2;
        __nv_bfloat16 ha = __float2bfloat16(r0[s0]), hb2 = __float2bfloat16(r0[s0 + 1]);
        hv[q] = __nv_bfloat162(ha, hb2);
        lv[q] = __nv_bfloat162(__float2bfloat16(r0[s0]     - __bfloat162float(ha)),
                               __float2bfloat16(r0[s0 + 1] - __bfloat162float(hb2)));
    }
    size_t o0 = (size_t)row * DHID + lane * 4;
    size_t o1 = (size_t)row * DHID + 128 + lane * 4;
    *(__nv_bfloat162*)(oh + o0)     = hv[0];
    *(__nv_bfloat162*)(oh + o0 + 2) = hv[1];
    *(__nv_bfloat162*)(oh + o1)     = hv[2];
    *(__nv_bfloat162*)(oh + o1 + 2) = hv[3];
    *(__nv_bfloat162*)(ol + o0)     = lv[0];
    *(__nv_bfloat162*)(ol + o0 + 2) = lv[1];
    *(__nv_bfloat162*)(ol + o1)     = lv[2];
    *(__nv_bfloat162*)(ol + o1 + 2) = lv[3];
}

// ---------------- 5) fused: f1/f2 per row + column partial sums ---------------
__global__ void k_feat(const float* __restrict__ h, const float* __restrict__ a) {
    __shared__ float sa1[DOUT], sa2[DOUT];
    const int b = blockIdx.x, tid = threadIdx.x;
    const int wid = tid >> 5, lane = tid & 31;
    if (tid < DOUT) { sa1[tid] = a[tid]; sa2[tid] = a[DOUT + tid]; }
    __syncthreads();

    const int r0 = b * 128;
#pragma unroll
    for (int rr = 0; rr < 16; rr++) {
        const int row = r0 + wid * 16 + rr;
        const float* hr = h + (size_t)row * DOUT;
        float s1 = 0.f, s2 = 0.f;
#pragma unroll
        for (int q = 0; q < 4; q++) {
            int c = lane + q * 32;
            float hv = hr[c];
            s1 = fmaf(hv, sa1[c], s1);
            s2 = fmaf(hv, sa2[c], s2);
        }
#pragma unroll
        for (int o = 16; o; o >>= 1) {
            s1 += __shfl_down_sync(0xffffffffu, s1, o);
            s2 += __shfl_down_sync(0xffffffffu, s2, o);
        }
        if (lane == 0) { g_f1[row] = s1; g_f2[row] = s2; }
    }

    if (tid < DOUT) {
        float s = 0.f;
        for (int r = 0; r < 128; r++) s += h[(size_t)(r0 + r) * DOUT + tid];
        g_part[b * DOUT + tid] = s;
    }
}
__global__ void k_mean() {
    const int c = threadIdx.x;
    float s = 0.f;
    for (int b = 0; b < 64; b++) s += g_part[b * DOUT + c];
    g_hmean[c] = s * (1.f / NN);
}

// ---------------- 6) warp-per-row softmax + h_prime (R10 form) ----------------
__global__ void __launch_bounds__(256) k_attn(const float* __restrict__ h,
                                              float* __restrict__ out) {
    const int row = blockIdx.x * 8 + (threadIdx.x >> 5);
    const int lane = threadIdx.x & 31;
    const int cnt = g_cnt[row];

    if (cnt == 0) {
        float4 v = ((const float4*)g_hmean)[lane];
        v.x = leaky(v.x); v.y = leaky(v.y); v.z = leaky(v.z); v.w = leaky(v.w);
        if (lane < 16) *(float4*)&out[(size_t)row * 64 + lane * 4] = v;
        else *(float4*)&out[(size_t)NN * 64 + (size_t)row * 64 + (lane - 16) * 4] = v;
        return;
    }

    const float f1i = g_f1[row];
    const int base = row * CAP;
    float ew[8]; int ec[8];
    float lmax = -INFINITY;
#pragma unroll
    for (int s = 0; s < 8; s++) {
        int t = lane + s * 32;
        if (t < cnt) {
            int j = g_ecol[base + t];
            float e = leaky(f1i + g_f2[j]);
            ec[s] = j; ew[s] = e;
            lmax = fmaxf(lmax, e);
        } else { ec[s] = 0; ew[s] = -INFINITY; }
    }
#pragma unroll
    for (int o = 16; o; o >>= 1) lmax = fmaxf(lmax, __shfl_xor_sync(0xffffffffu, lmax, o));

    float lsum = 0.f;
#pragma unroll
    for (int s = 0; s < 8; s++) {
        float w = (lane + s * 32 < cnt) ? __expf(ew[s] - lmax) : 0.f;
        ew[s] = w;
        lsum += w;
    }
#pragma unroll
    for (int o = 16; o; o >>= 1) lsum += __shfl_xor_sync(0xffffffffu, lsum, o);
    const float invZ = 1.f / lsum;

    float4 acc = make_float4(0.f, 0.f, 0.f, 0.f);
    const int nslots = (cnt + 31) >> 5;
    for (int s = 0; s < nslots; s++) {
        const int lim = min(32, cnt - s * 32);
        for (int u = 0; u < lim; u++) {
            const float w = __shfl_sync(0xffffffffu, ew[s], u);
            const int   j = __shfl_sync(0xffffffffu, ec[s], u);
            float4 v = ((const float4*)(h + (size_t)j * DOUT))[lane];
            acc.x = fmaf(w, v.x, acc.x); acc.y = fmaf(w, v.y, acc.y);
            acc.z = fmaf(w, v.z, acc.z); acc.w = fmaf(w, v.w, acc.w);
        }
    }
    float4 r = make_float4(leaky(acc.x * invZ), leaky(acc.y * invZ),
                           leaky(acc.z * invZ), leaky(acc.w * invZ));
    if (lane < 16) *(float4*)&out[(size_t)row * 64 + lane * 4] = r;
    else *(float4*)&out[(size_t)NN * 64 + (size_t)row * 64 + (lane - 16) * 4] = r;
}

// ---------------- launch -----------------------------------------------------
extern "C" void kernel_launch(void* const* d_in, const int* in_sizes, int n_in,
                              void* d_out, int out_size) {
    (void)in_sizes; (void)n_in; (void)out_size;
    const float* x   = (const float*)d_in[0];
    const float* adj = (const float*)d_in[1];
    const float* W1  = (const float*)d_in[2];
    const float* b1  = (const float*)d_in[3];
    const float* W2  = (const float*)d_in[4];
    const float* b2  = (const float*)d_in[5];
    const float* Wg  = (const float*)d_in[6];
    const float* a   = (const float*)d_in[7];
    float* out = (float*)d_out;

    void* p;
    cudaGetSymbolAddress(&p, g_y1);   float* y1 = (float*)p;
    cudaGetSymbolAddress(&p, g_y2);   float* y2 = (float*)p;
    cudaGetSymbolAddress(&p, g_h);    float* h  = (float*)p;
    cudaGetSymbolAddress(&p, g_xh);   __nv_bfloat16* xh  = (__nv_bfloat16*)p;
    cudaGetSymbolAddress(&p, g_xl);   __nv_bfloat16* xl  = (__nv_bfloat16*)p;
    cudaGetSymbolAddress(&p, g_x1h);  __nv_bfloat16* x1h = (__nv_bfloat16*)p;
    cudaGetSymbolAddress(&p, g_x1l);  __nv_bfloat16* x1l = (__nv_bfloat16*)p;
    cudaGetSymbolAddress(&p, g_x2h);  __nv_bfloat16* x2h = (__nv_bfloat16*)p;
    cudaGetSymbolAddress(&p, g_x2l);  __nv_bfloat16* x2l = (__nv_bfloat16*)p;
    cudaGetSymbolAddress(&p, g_w1th); __nv_bfloat16* w1th = (__nv_bfloat16*)p;
    cudaGetSymbolAddress(&p, g_w1tl); __nv_bfloat16* w1tl = (__nv_bfloat16*)p;
    cudaGetSymbolAddress(&p, g_w2th); __nv_bfloat16* w2th = (__nv_bfloat16*)p;
    cudaGetSymbolAddress(&p, g_w2tl); __nv_bfloat16* w2tl = (__nv_bfloat16*)p;
    cudaGetSymbolAddress(&p, g_wgth); __nv_bfloat16* wgth = (__nv_bfloat16*)p;
    cudaGetSymbolAddress(&p, g_wgtl); __nv_bfloat16* wgtl = (__nv_bfloat16*)p;

    constexpr int SMEM_BIG   = 3 * (2 * 128 * SPAD * 2 + 2 * 128 * SPAD * 2); // 122880
    constexpr int SMEM_SMALL = 3 * (2 * 64 * SPAD * 2 + 2 * 128 * SPAD * 2);  // 92160

    static cudaStream_t s2 = nullptr;
    static cudaEvent_t ev_fork = nullptr, ev_extract = nullptr;
    if (!s2) {
        cudaStreamCreateWithFlags(&s2, cudaStreamNonBlocking);
        cudaEventCreateWithFlags(&ev_fork, cudaEventDisableTiming);
        cudaEventCreateWithFlags(&ev_extract, cudaEventDisableTiming);
        cudaFuncSetAttribute(k_hmma<128, 128, 4, 4>, cudaFuncAttributeMaxDynamicSharedMemorySize, SMEM_BIG);
        cudaFuncSetAttribute(k_hmma<64, 128, 2, 4>,  cudaFuncAttributeMaxDynamicSharedMemorySize, SMEM_SMALL);
    }

    cudaEventRecord(ev_fork, 0);
    cudaStreamWaitEvent(s2, ev_fork, 0);
    k_extract<<<256, 256, 0, s2>>>(adj);          // 256 blocks -> co-resident
    cudaEventRecord(ev_extract, s2);

    k_prep<<<4320, 256>>>(x, W1, W2, Wg);
    k_hmma<128, 128, 4, 4><<<dim3(NN / 128, DHID / 128), 512, SMEM_BIG>>>(
        xh, xl, w1th, w1tl, y1, DHID, DIN);

    cudaStreamWaitEvent(0, ev_extract, 0);
    k_spmm<<<NN / 8, 256>>>(y1, b1, x1h, x1l);
    k_hmma<128, 128, 4, 4><<<dim3(NN / 128, DHID / 128), 512, SMEM_BIG>>>(
        x1h, x1l, w2th, w2tl, y2, DHID, DHID);
    k_spmm<<<NN / 8, 256>>>(y2, b2, x2h, x2l);
    k_hmma<64, 128, 2, 4><<<dim3(NN / 64, DOUT / 128), 256, SMEM_SMALL>>>(
        x2h, x2l, wgth, wgtl, h, DOUT, DHID);

    k_feat<<<64, 256>>>(h, a);
    k_mean<<<1, 128>>>();
    k_attn<<<NN / 8, 256>>>(h, out);
}

// round 15
// speedup vs baseline: 1.3446x; 1.3446x over previous
#include <cuda_runtime.h>
#include <cuda_bf16.h>
#include <math.h>
#include <stdint.h>

#define NN   8192
#define DIN  512
#define DHID 256
#define DOUT 128
#define CAP  256
#define NEG  0.25f

// ---------------- scratch (device globals) ----------------------------------
__device__ float g_y1[NN * DHID];
__device__ float g_y2[NN * DHID];
__device__ float g_h [NN * DOUT];
__device__ float g_f1[NN];
__device__ float g_f2[NN];
__device__ int   g_cnt [NN];
__device__ int   g_ecol[NN * CAP];
__device__ float g_eval[NN * CAP];
__device__ float g_part[64 * DOUT];
__device__ float g_hmean[DOUT];

__device__ __nv_bfloat16 g_xh [NN * DIN],  g_xl [NN * DIN];
__device__ __nv_bfloat16 g_x1h[NN * DHID], g_x1l[NN * DHID];
__device__ __nv_bfloat16 g_x2h[NN * DHID], g_x2l[NN * DHID];
__device__ __nv_bfloat16 g_w1th[DHID * DIN],  g_w1tl[DHID * DIN];
__device__ __nv_bfloat16 g_w2th[DHID * DHID], g_w2tl[DHID * DHID];
__device__ __nv_bfloat16 g_wgth[DOUT * DHID], g_wgtl[DOUT * DHID];

__device__ __forceinline__ float leaky(float x) { return x >= 0.f ? x : NEG * x; }

__device__ __forceinline__ uint32_t smem_to_u32(const void* p) {
    uint32_t a;
    asm("{ .reg .u64 t; cvta.to.shared.u64 t, %1; cvt.u32.u64 %0, t; }" : "=r"(a) : "l"(p));
    return a;
}
__device__ __forceinline__ void ldsm_x4(uint32_t* r, uint32_t addr) {
    asm volatile("ldmatrix.sync.aligned.m8n8.x4.shared.b16 {%0,%1,%2,%3}, [%4];"
                 : "=r"(r[0]), "=r"(r[1]), "=r"(r[2]), "=r"(r[3]) : "r"(addr));
}
__device__ __forceinline__ void mma16816(float* c, const uint32_t* a, uint32_t b0, uint32_t b1) {
    asm volatile("mma.sync.aligned.m16n8k16.row.col.f32.bf16.bf16.f32 "
                 "{%0,%1,%2,%3}, {%4,%5,%6,%7}, {%8,%9}, {%0,%1,%2,%3};"
                 : "+f"(c[0]), "+f"(c[1]), "+f"(c[2]), "+f"(c[3])
                 : "r"(a[0]), "r"(a[1]), "r"(a[2]), "r"(a[3]), "r"(b0), "r"(b1));
}
__device__ __forceinline__ void cp16(uint32_t saddr, const void* g) {
    asm volatile("cp.async.ca.shared.global [%0], [%1], 16;" :: "r"(saddr), "l"(g));
}
#define CP_COMMIT() asm volatile("cp.async.commit_group;" ::: "memory")
#define CP_WAIT(n)  asm volatile("cp.async.wait_group %0;" :: "n"(n) : "memory")

// ---------------- 1) edge extraction: warp-per-row, zero smem -----------------
// Warp w scans row w in 256 coalesced rounds; ballot/popc compaction.
// 1024 blocks x 256 thr, no smem, low regs -> co-resides with anything.
__global__ void __launch_bounds__(256) k_extract(const float* __restrict__ adj) {
    const int row = blockIdx.x * 8 + (threadIdx.x >> 5);
    const int lane = threadIdx.x & 31;
    const float* arow = adj + (size_t)row * NN;
    const int base = row * CAP;
    const uint32_t below = (1u << lane) - 1u;

    int off = 0;
    for (int r = 0; r < 256; r += 4) {
        // 4 independent coalesced loads -> MLP 4
        float v0 = arow[(r + 0) * 32 + lane];
        float v1 = arow[(r + 1) * 32 + lane];
        float v2 = arow[(r + 2) * 32 + lane];
        float v3 = arow[(r + 3) * 32 + lane];
#pragma unroll
        for (int q = 0; q < 4; q++) {
            float v = q == 0 ? v0 : q == 1 ? v1 : q == 2 ? v2 : v3;
            uint32_t m = __ballot_sync(0xffffffffu, v > 0.f);
            if (v > 0.f) {
                int p = off + __popc(m & below);
                if (p < CAP) { g_ecol[base + p] = (r + q) * 32 + lane; g_eval[base + p] = v; }
            }
            off += __popc(m);
        }
    }
    if (lane == 0) g_cnt[row] = off < CAP ? off : CAP;
}

// ---------------- 2) fused prep: x split + W transposes -----------------------
__global__ void k_prep(const float* __restrict__ x,
                       const float* __restrict__ W1, const float* __restrict__ W2,
                       const float* __restrict__ Wg) {
    int b = blockIdx.x;
    if (b < 4096) {
        int i = b * 256 + threadIdx.x;
        float4 v = ((const float4*)x)[i];
        __nv_bfloat16 h0 = __float2bfloat16(v.x), h1 = __float2bfloat16(v.y);
        __nv_bfloat16 h2 = __float2bfloat16(v.z), h3 = __float2bfloat16(v.w);
        __nv_bfloat162* hp = (__nv_bfloat162*)g_xh;
        __nv_bfloat162* lp = (__nv_bfloat162*)g_xl;
        hp[2 * i]     = __nv_bfloat162(h0, h1);
        hp[2 * i + 1] = __nv_bfloat162(h2, h3);
        lp[2 * i]     = __nv_bfloat162(__float2bfloat16(v.x - __bfloat162float(h0)),
                                       __float2bfloat16(v.y - __bfloat162float(h1)));
        lp[2 * i + 1] = __nv_bfloat162(__float2bfloat16(v.z - __bfloat162float(h2)),
                                       __float2bfloat16(v.w - __bfloat162float(h3)));
        return;
    }
    b -= 4096;
    __shared__ float tile[32][33];
    const float* W; __nv_bfloat16 *th, *tl; int K, N, tk, tn;
    if (b < 128) {
        W = W1; th = g_w1th; tl = g_w1tl; K = DIN; N = DHID;
        tk = (b >> 3) * 32; tn = (b & 7) * 32;
    } else if (b < 192) {
        b -= 128; W = W2; th = g_w2th; tl = g_w2tl; K = DHID; N = DHID;
        tk = (b >> 3) * 32; tn = (b & 7) * 32;
    } else {
        b -= 192; W = Wg; th = g_wgth; tl = g_wgtl; K = DHID; N = DOUT;
        tk = (b >> 2) * 32; tn = (b & 3) * 32;
    }
    const int tx = threadIdx.x & 31, ty = threadIdx.x >> 5;
#pragma unroll
    for (int i = 0; i < 32; i += 8)
        tile[ty + i][tx] = W[(size_t)(tk + ty + i) * N + tn + tx];
    __syncthreads();
#pragma unroll
    for (int i = 0; i < 32; i += 8) {
        float v = tile[tx][ty + i];
        __nv_bfloat16 hb = __float2bfloat16(v);
        size_t o = (size_t)(tn + ty + i) * K + tk + tx;
        th[o] = hb;
        tl[o] = __float2bfloat16(v - __bfloat162float(hb));
    }
}

// ---------------- 3) 3-stage pipelined HMMA bf16-split GEMM ------------------
#define SPAD 40
template<int BM, int BN, int WM, int WN>
__global__ void __launch_bounds__(WM * WN * 32) k_hmma(
    const __nv_bfloat16* __restrict__ Ah, const __nv_bfloat16* __restrict__ Al,
    const __nv_bfloat16* __restrict__ Bh, const __nv_bfloat16* __restrict__ Bl,
    float* __restrict__ C, int N, int K)
{
    constexpr int T = WM * WN * 32;
    constexpr int ARR_A = BM * SPAD * 2;
    constexpr int ARR_BB = BN * SPAD * 2;
    constexpr int OFF_AH = 0;
    constexpr int OFF_AL = ARR_A;
    constexpr int OFF_BH = 2 * ARR_A;
    constexpr int OFF_BL = 2 * ARR_A + ARR_BB;
    constexpr int STAGE  = 2 * ARR_A + 2 * ARR_BB;

    extern __shared__ char dsm[];
    const uint32_t sb = smem_to_u32(dsm);
    const int tid = threadIdx.x, wid = tid >> 5, lane = tid & 31;
    const int m0 = blockIdx.x * BM, n0 = blockIdx.y * BN;
    const int wm = (wid % WM) * 32, wn = (wid / WM) * 32;

    float acc[2][4][4];
#pragma unroll
    for (int i = 0; i < 2; i++)
#pragma unroll
        for (int j = 0; j < 4; j++)
#pragma unroll
            for (int q = 0; q < 4; q++) acc[i][j][q] = 0.f;

    const int nch = K >> 5;

    auto issue = [&](int kc) {
        const uint32_t st = sb + (kc % 3) * STAGE;
#pragma unroll
        for (int idx = tid; idx < BM * 4; idx += T) {
            const int r = idx >> 2, c = idx & 3;
            const uint32_t so = (uint32_t)(r * SPAD + c * 8) * 2;
            const size_t gA = (size_t)(m0 + r) * K + kc * 32 + c * 8;
            cp16(st + OFF_AH + so, Ah + gA);
            cp16(st + OFF_AL + so, Al + gA);
        }
#pragma unroll
        for (int idx = tid; idx < BN * 4; idx += T) {
            const int r = idx >> 2, c = idx & 3;
            const uint32_t so = (uint32_t)(r * SPAD + c * 8) * 2;
            const size_t gB = (size_t)(n0 + r) * K + kc * 32 + c * 8;
            cp16(st + OFF_BH + so, Bh + gB);
            cp16(st + OFF_BL + so, Bl + gB);
        }
        CP_COMMIT();
    };

    issue(0);
    issue(1);

    for (int kc = 0; kc < nch; kc++) {
        if (kc + 1 < nch) { CP_WAIT(1); } else { CP_WAIT(0); }
        __syncthreads();
        if (kc + 2 < nch) issue(kc + 2);

        const uint32_t st = sb + (kc % 3) * STAGE;
#pragma unroll
        for (int ks = 0; ks < 2; ks++) {
            const int kb = ks * 16;
            const uint32_t aoff = ((wm + (lane & 15)) * SPAD + kb + 8 * (lane >> 4)) * 2;
            uint32_t afr[2][2][4];
            ldsm_x4(afr[0][0], st + OFF_AH + aoff);
            ldsm_x4(afr[0][1], st + OFF_AL + aoff);
            ldsm_x4(afr[1][0], st + OFF_AH + aoff + 16 * SPAD * 2);
            ldsm_x4(afr[1][1], st + OFF_AL + aoff + 16 * SPAD * 2);
            const uint32_t boff = ((wn + 8 * (lane >> 4) + (lane & 7)) * SPAD
                                   + kb + 8 * ((lane >> 3) & 1)) * 2;
            uint32_t bfr[2][2][4];
            ldsm_x4(bfr[0][0], st + OFF_BH + boff);
            ldsm_x4(bfr[0][1], st + OFF_BL + boff);
            ldsm_x4(bfr[1][0], st + OFF_BH + boff + 16 * SPAD * 2);
            ldsm_x4(bfr[1][1], st + OFF_BL + boff + 16 * SPAD * 2);

#pragma unroll
            for (int i = 0; i < 2; i++)
#pragma unroll
                for (int j = 0; j < 4; j++) {
                    const int p = j >> 1, s = (j & 1) * 2;
                    mma16816(acc[i][j], afr[i][0], bfr[p][0][s], bfr[p][0][s + 1]);
                    mma16816(acc[i][j], afr[i][0], bfr[p][1][s], bfr[p][1][s + 1]);
                    mma16816(acc[i][j], afr[i][1], bfr[p][0][s], bfr[p][0][s + 1]);
                }
        }
    }

    const int g = lane >> 2, t2 = (lane & 3) * 2;
#pragma unroll
    for (int i = 0; i < 2; i++)
#pragma unroll
        for (int j = 0; j < 4; j++) {
            const int rm = m0 + wm + 16 * i + g;
            const int cn = n0 + wn + 8 * j + t2;
            *(float2*)&C[(size_t)rm * N + cn]       = make_float2(acc[i][j][0], acc[i][j][1]);
            *(float2*)&C[(size_t)(rm + 8) * N + cn] = make_float2(acc[i][j][2], acc[i][j][3]);
        }
}

// ---------------- 4) warp-per-row SpMM (R10 form: reg-staged, shfl) -----------
__global__ void __launch_bounds__(256) k_spmm(
    const float* __restrict__ y, const float* __restrict__ bias,
    __nv_bfloat16* __restrict__ oh, __nv_bfloat16* __restrict__ ol) {
    const int row = blockIdx.x * 8 + (threadIdx.x >> 5);
    const int lane = threadIdx.x & 31;
    const int cnt = g_cnt[row];

    float ev[8]; int ec[8];
    const int base = row * CAP;
#pragma unroll
    for (int s = 0; s < 8; s++) {
        int t = lane + s * 32;
        if (t < cnt) { ec[s] = g_ecol[base + t]; ev[s] = g_eval[base + t]; }
        else         { ec[s] = 0;               ev[s] = 0.f; }
    }

    float4 acc0 = make_float4(0.f, 0.f, 0.f, 0.f);
    float4 acc1 = make_float4(0.f, 0.f, 0.f, 0.f);
    const int nslots = (cnt + 31) >> 5;
    for (int s = 0; s < nslots; s++) {
        const int lim = min(32, cnt - s * 32);
        for (int u = 0; u < lim; u++) {
            const float w = __shfl_sync(0xffffffffu, ev[s], u);
            const int   j = __shfl_sync(0xffffffffu, ec[s], u);
            const float4* yr = (const float4*)(y + (size_t)j * DHID);
            float4 v0 = yr[lane];
            float4 v1 = yr[lane + 32];
            acc0.x = fmaf(w, v0.x, acc0.x); acc0.y = fmaf(w, v0.y, acc0.y);
            acc0.z = fmaf(w, v0.z, acc0.z); acc0.w = fmaf(w, v0.w, acc0.w);
            acc1.x = fmaf(w, v1.x, acc1.x); acc1.y = fmaf(w, v1.y, acc1.y);
            acc1.z = fmaf(w, v1.z, acc1.z); acc1.w = fmaf(w, v1.w, acc1.w);
        }
    }
    const float4 b0 = ((const float4*)bias)[lane];
    const float4 b1 = ((const float4*)bias)[lane + 32];
    float r0[8] = { leaky(acc0.x + b0.x), leaky(acc0.y + b0.y),
                    leaky(acc0.z + b0.z), leaky(acc0.w + b0.w),
                    leaky(acc1.x + b1.x), leaky(acc1.y + b1.y),
                    leaky(acc1.z + b1.z), leaky(acc1.w + b1.w) };
    __nv_bfloat162 hv[4], lv[4];
#pragma unroll
    for (int q = 0; q < 4; q++) {
        int s0 = q * 2;
        __nv_bfloat16 ha = __float2bfloat16(r0[s0]), hb2 = __float2bfloat16(r0[s0 + 1]);
        hv[q] = __nv_bfloat162(ha, hb2);
        lv[q] = __nv_bfloat162(__float2bfloat16(r0[s0]     - __bfloat162float(ha)),
                               __float2bfloat16(r0[s0 + 1] - __bfloat162float(hb2)));
    }
    size_t o0 = (size_t)row * DHID + lane * 4;
    size_t o1 = (size_t)row * DHID + 128 + lane * 4;
    *(__nv_bfloat162*)(oh + o0)     = hv[0];
    *(__nv_bfloat162*)(oh + o0 + 2) = hv[1];
    *(__nv_bfloat162*)(oh + o1)     = hv[2];
    *(__nv_bfloat162*)(oh + o1 + 2) = hv[3];
    *(__nv_bfloat162*)(ol + o0)     = lv[0];
    *(__nv_bfloat162*)(ol + o0 + 2) = lv[1];
    *(__nv_bfloat162*)(ol + o1)     = lv[2];
    *(__nv_bfloat162*)(ol + o1 + 2) = lv[3];
}

// ---------------- 5) fused: f1/f2 per row + column partial sums ---------------
__global__ void k_feat(const float* __restrict__ h, const float* __restrict__ a) {
    __shared__ float sa1[DOUT], sa2[DOUT];
    const int b = blockIdx.x, tid = threadIdx.x;
    const int wid = tid >> 5, lane = tid & 31;
    if (tid < DOUT) { sa1[tid] = a[tid]; sa2[tid] = a[DOUT + tid]; }
    __syncthreads();

    const int r0 = b * 128;
#pragma unroll
    for (int rr = 0; rr < 16; rr++) {
        const int row = r0 + wid * 16 + rr;
        const float* hr = h + (size_t)row * DOUT;
        float s1 = 0.f, s2 = 0.f;
#pragma unroll
        for (int q = 0; q < 4; q++) {
            int c = lane + q * 32;
            float hv = hr[c];
            s1 = fmaf(hv, sa1[c], s1);
            s2 = fmaf(hv, sa2[c], s2);
        }
#pragma unroll
        for (int o = 16; o; o >>= 1) {
            s1 += __shfl_down_sync(0xffffffffu, s1, o);
            s2 += __shfl_down_sync(0xffffffffu, s2, o);
        }
        if (lane == 0) { g_f1[row] = s1; g_f2[row] = s2; }
    }

    if (tid < DOUT) {
        float s = 0.f;
        for (int r = 0; r < 128; r++) s += h[(size_t)(r0 + r) * DOUT + tid];
        g_part[b * DOUT + tid] = s;
    }
}
__global__ void k_mean() {
    const int c = threadIdx.x;
    float s = 0.f;
    for (int b = 0; b < 64; b++) s += g_part[b * DOUT + c];
    g_hmean[c] = s * (1.f / NN);
}

// ---------------- 6) warp-per-row softmax + h_prime (R10 form) ----------------
__global__ void __launch_bounds__(256) k_attn(const float* __restrict__ h,
                                              float* __restrict__ out) {
    const int row = blockIdx.x * 8 + (threadIdx.x >> 5);
    const int lane = threadIdx.x & 31;
    const int cnt = g_cnt[row];

    if (cnt == 0) {
        float4 v = ((const float4*)g_hmean)[lane];
        v.x = leaky(v.x); v.y = leaky(v.y); v.z = leaky(v.z); v.w = leaky(v.w);
        if (lane < 16) *(float4*)&out[(size_t)row * 64 + lane * 4] = v;
        else *(float4*)&out[(size_t)NN * 64 + (size_t)row * 64 + (lane - 16) * 4] = v;
        return;
    }

    const float f1i = g_f1[row];
    const int base = row * CAP;
    float ew[8]; int ec[8];
    float lmax = -INFINITY;
#pragma unroll
    for (int s = 0; s < 8; s++) {
        int t = lane + s * 32;
        if (t < cnt) {
            int j = g_ecol[base + t];
            float e = leaky(f1i + g_f2[j]);
            ec[s] = j; ew[s] = e;
            lmax = fmaxf(lmax, e);
        } else { ec[s] = 0; ew[s] = -INFINITY; }
    }
#pragma unroll
    for (int o = 16; o; o >>= 1) lmax = fmaxf(lmax, __shfl_xor_sync(0xffffffffu, lmax, o));

    float lsum = 0.f;
#pragma unroll
    for (int s = 0; s < 8; s++) {
        float w = (lane + s * 32 < cnt) ? __expf(ew[s] - lmax) : 0.f;
        ew[s] = w;
        lsum += w;
    }
#pragma unroll
    for (int o = 16; o; o >>= 1) lsum += __shfl_xor_sync(0xffffffffu, lsum, o);
    const float invZ = 1.f / lsum;

    float4 acc = make_float4(0.f, 0.f, 0.f, 0.f);
    const int nslots = (cnt + 31) >> 5;
    for (int s = 0; s < nslots; s++) {
        const int lim = min(32, cnt - s * 32);
        for (int u = 0; u < lim; u++) {
            const float w = __shfl_sync(0xffffffffu, ew[s], u);
            const int   j = __shfl_sync(0xffffffffu, ec[s], u);
            float4 v = ((const float4*)(h + (size_t)j * DOUT))[lane];
            acc.x = fmaf(w, v.x, acc.x); acc.y = fmaf(w, v.y, acc.y);
            acc.z = fmaf(w, v.z, acc.z); acc.w = fmaf(w, v.w, acc.w);
        }
    }
    float4 r = make_float4(leaky(acc.x * invZ), leaky(acc.y * invZ),
                           leaky(acc.z * invZ), leaky(acc.w * invZ));
    if (lane < 16) *(float4*)&out[(size_t)row * 64 + lane * 4] = r;
    else *(float4*)&out[(size_t)NN * 64 + (size_t)row * 64 + (lane - 16) * 4] = r;
}

// ---------------- launch -----------------------------------------------------
extern "C" void kernel_launch(void* const* d_in, const int* in_sizes, int n_in,
                              void* d_out, int out_size) {
    (void)in_sizes; (void)n_in; (void)out_size;
    const float* x   = (const float*)d_in[0];
    const float* adj = (const float*)d_in[1];
    const float* W1  = (const float*)d_in[2];
    const float* b1  = (const float*)d_in[3];
    const float* W2  = (const float*)d_in[4];
    const float* b2  = (const float*)d_in[5];
    const float* Wg  = (const float*)d_in[6];
    const float* a   = (const float*)d_in[7];
    float* out = (float*)d_out;

    void* p;
    cudaGetSymbolAddress(&p, g_y1);   float* y1 = (float*)p;
    cudaGetSymbolAddress(&p, g_y2);   float* y2 = (float*)p;
    cudaGetSymbolAddress(&p, g_h);    float* h  = (float*)p;
    cudaGetSymbolAddress(&p, g_xh);   __nv_bfloat16* xh  = (__nv_bfloat16*)p;
    cudaGetSymbolAddress(&p, g_xl);   __nv_bfloat16* xl  = (__nv_bfloat16*)p;
    cudaGetSymbolAddress(&p, g_x1h);  __nv_bfloat16* x1h = (__nv_bfloat16*)p;
    cudaGetSymbolAddress(&p, g_x1l);  __nv_bfloat16* x1l = (__nv_bfloat16*)p;
    cudaGetSymbolAddress(&p, g_x2h);  __nv_bfloat16* x2h = (__nv_bfloat16*)p;
    cudaGetSymbolAddress(&p, g_x2l);  __nv_bfloat16* x2l = (__nv_bfloat16*)p;
    cudaGetSymbolAddress(&p, g_w1th); __nv_bfloat16* w1th = (__nv_bfloat16*)p;
    cudaGetSymbolAddress(&p, g_w1tl); __nv_bfloat16* w1tl = (__nv_bfloat16*)p;
    cudaGetSymbolAddress(&p, g_w2th); __nv_bfloat16* w2th = (__nv_bfloat16*)p;
    cudaGetSymbolAddress(&p, g_w2tl); __nv_bfloat16* w2tl = (__nv_bfloat16*)p;
    cudaGetSymbolAddress(&p, g_wgth); __nv_bfloat16* wgth = (__nv_bfloat16*)p;
    cudaGetSymbolAddress(&p, g_wgtl); __nv_bfloat16* wgtl = (__nv_bfloat16*)p;

    constexpr int SMEM_BIG   = 3 * (2 * 128 * SPAD * 2 + 2 * 128 * SPAD * 2); // 122880
    constexpr int SMEM_SMALL = 3 * (2 * 64 * SPAD * 2 + 2 * 128 * SPAD * 2);  // 92160

    static cudaStream_t s2 = nullptr;
    static cudaEvent_t ev_fork = nullptr, ev_extract = nullptr;
    if (!s2) {
        cudaStreamCreateWithFlags(&s2, cudaStreamNonBlocking);
        cudaEventCreateWithFlags(&ev_fork, cudaEventDisableTiming);
        cudaEventCreateWithFlags(&ev_extract, cudaEventDisableTiming);
        cudaFuncSetAttribute(k_hmma<128, 128, 4, 4>, cudaFuncAttributeMaxDynamicSharedMemorySize, SMEM_BIG);
        cudaFuncSetAttribute(k_hmma<64, 128, 2, 4>,  cudaFuncAttributeMaxDynamicSharedMemorySize, SMEM_SMALL);
    }

    cudaEventRecord(ev_fork, 0);
    cudaStreamWaitEvent(s2, ev_fork, 0);
    k_extract<<<NN / 8, 256, 0, s2>>>(adj);       // zero-smem, co-resident
    cudaEventRecord(ev_extract, s2);

    k_prep<<<4320, 256>>>(x, W1, W2, Wg);
    k_hmma<128, 128, 4, 4><<<dim3(NN / 128, DHID / 128), 512, SMEM_BIG>>>(
        xh, xl, w1th, w1tl, y1, DHID, DIN);

    cudaStreamWaitEvent(0, ev_extract, 0);
    k_spmm<<<NN / 8, 256>>>(y1, b1, x1h, x1l);
    k_hmma<128, 128, 4, 4><<<dim3(NN / 128, DHID / 128), 512, SMEM_BIG>>>(
        x1h, x1l, w2th, w2tl, y2, DHID, DHID);
    k_spmm<<<NN / 8, 256>>>(y2, b2, x2h, x2l);
    k_hmma<64, 128, 2, 4><<<dim3(NN / 64, DOUT / 128), 256, SMEM_SMALL>>>(
        x2h, x2l, wgth, wgtl, h, DOUT, DHID);

    k_feat<<<64, 256>>>(h, a);
    k_mean<<<1, 128>>>();
    k_attn<<<NN / 8, 256>>>(h, out);
}

// round 16
// speedup vs baseline: 1.4007x; 1.0417x over previous
#include <cuda_runtime.h>
#include <cuda_bf16.h>
#include <math.h>
#include <stdint.h>

#define NN   8192
#define DIN  512
#define DHID 256
#define DOUT 128
#define CAP  256
#define NEG  0.25f

// ---------------- scratch (device globals) ----------------------------------
__device__ float g_y1[NN * DHID];
__device__ float g_y2[NN * DHID];
__device__ float g_h [NN * DOUT];
__device__ float g_f1[NN];
__device__ float g_f2[NN];
__device__ int   g_cnt [NN];
__device__ int   g_ecol[NN * CAP];
__device__ float g_eval[NN * CAP];
__device__ float g_part[64 * DOUT];
__device__ float g_hmean[DOUT];

__device__ __nv_bfloat16 g_xh [NN * DIN],  g_xl [NN * DIN];
__device__ __nv_bfloat16 g_x1h[NN * DHID], g_x1l[NN * DHID];
__device__ __nv_bfloat16 g_x2h[NN * DHID], g_x2l[NN * DHID];
__device__ __nv_bfloat16 g_w1th[DHID * DIN],  g_w1tl[DHID * DIN];
__device__ __nv_bfloat16 g_w2th[DHID * DHID], g_w2tl[DHID * DHID];
__device__ __nv_bfloat16 g_wgth[DOUT * DHID], g_wgtl[DOUT * DHID];

__device__ __forceinline__ float leaky(float x) { return x >= 0.f ? x : NEG * x; }

__device__ __forceinline__ uint32_t smem_to_u32(const void* p) {
    uint32_t a;
    asm("{ .reg .u64 t; cvta.to.shared.u64 t, %1; cvt.u32.u64 %0, t; }" : "=r"(a) : "l"(p));
    return a;
}
__device__ __forceinline__ void ldsm_x4(uint32_t* r, uint32_t addr) {
    asm volatile("ldmatrix.sync.aligned.m8n8.x4.shared.b16 {%0,%1,%2,%3}, [%4];"
                 : "=r"(r[0]), "=r"(r[1]), "=r"(r[2]), "=r"(r[3]) : "r"(addr));
}
__device__ __forceinline__ void mma16816(float* c, const uint32_t* a, uint32_t b0, uint32_t b1) {
    asm volatile("mma.sync.aligned.m16n8k16.row.col.f32.bf16.bf16.f32 "
                 "{%0,%1,%2,%3}, {%4,%5,%6,%7}, {%8,%9}, {%0,%1,%2,%3};"
                 : "+f"(c[0]), "+f"(c[1]), "+f"(c[2]), "+f"(c[3])
                 : "r"(a[0]), "r"(a[1]), "r"(a[2]), "r"(a[3]), "r"(b0), "r"(b1));
}
__device__ __forceinline__ void cp16(uint32_t saddr, const void* g) {
    asm volatile("cp.async.ca.shared.global [%0], [%1], 16;" :: "r"(saddr), "l"(g));
}
#define CP_COMMIT() asm volatile("cp.async.commit_group;" ::: "memory")
#define CP_WAIT(n)  asm volatile("cp.async.wait_group %0;" :: "n"(n) : "memory")

// ---------------- 1) edge extraction: warp-per-row, zero smem -----------------
__global__ void __launch_bounds__(256) k_extract(const float* __restrict__ adj) {
    const int row = blockIdx.x * 8 + (threadIdx.x >> 5);
    const int lane = threadIdx.x & 31;
    const float* arow = adj + (size_t)row * NN;
    const int base = row * CAP;
    const uint32_t below = (1u << lane) - 1u;

    int off = 0;
    for (int r = 0; r < 256; r += 4) {
        float v0 = arow[(r + 0) * 32 + lane];
        float v1 = arow[(r + 1) * 32 + lane];
        float v2 = arow[(r + 2) * 32 + lane];
        float v3 = arow[(r + 3) * 32 + lane];
#pragma unroll
        for (int q = 0; q < 4; q++) {
            float v = q == 0 ? v0 : q == 1 ? v1 : q == 2 ? v2 : v3;
            uint32_t m = __ballot_sync(0xffffffffu, v > 0.f);
            if (v > 0.f) {
                int p = off + __popc(m & below);
                if (p < CAP) { g_ecol[base + p] = (r + q) * 32 + lane; g_eval[base + p] = v; }
            }
            off += __popc(m);
        }
    }
    if (lane == 0) g_cnt[row] = off < CAP ? off : CAP;
}

// ---------------- 2) fused prep: x split + W transposes -----------------------
__global__ void k_prep(const float* __restrict__ x,
                       const float* __restrict__ W1, const float* __restrict__ W2,
                       const float* __restrict__ Wg) {
    int b = blockIdx.x;
    if (b < 4096) {
        int i = b * 256 + threadIdx.x;
        float4 v = ((const float4*)x)[i];
        __nv_bfloat16 h0 = __float2bfloat16(v.x), h1 = __float2bfloat16(v.y);
        __nv_bfloat16 h2 = __float2bfloat16(v.z), h3 = __float2bfloat16(v.w);
        __nv_bfloat162* hp = (__nv_bfloat162*)g_xh;
        __nv_bfloat162* lp = (__nv_bfloat162*)g_xl;
        hp[2 * i]     = __nv_bfloat162(h0, h1);
        hp[2 * i + 1] = __nv_bfloat162(h2, h3);
        lp[2 * i]     = __nv_bfloat162(__float2bfloat16(v.x - __bfloat162float(h0)),
                                       __float2bfloat16(v.y - __bfloat162float(h1)));
        lp[2 * i + 1] = __nv_bfloat162(__float2bfloat16(v.z - __bfloat162float(h2)),
                                       __float2bfloat16(v.w - __bfloat162float(h3)));
        return;
    }
    b -= 4096;
    __shared__ float tile[32][33];
    const float* W; __nv_bfloat16 *th, *tl; int K, N, tk, tn;
    if (b < 128) {
        W = W1; th = g_w1th; tl = g_w1tl; K = DIN; N = DHID;
        tk = (b >> 3) * 32; tn = (b & 7) * 32;
    } else if (b < 192) {
        b -= 128; W = W2; th = g_w2th; tl = g_w2tl; K = DHID; N = DHID;
        tk = (b >> 3) * 32; tn = (b & 7) * 32;
    } else {
        b -= 192; W = Wg; th = g_wgth; tl = g_wgtl; K = DHID; N = DOUT;
        tk = (b >> 2) * 32; tn = (b & 3) * 32;
    }
    const int tx = threadIdx.x & 31, ty = threadIdx.x >> 5;
#pragma unroll
    for (int i = 0; i < 32; i += 8)
        tile[ty + i][tx] = W[(size_t)(tk + ty + i) * N + tn + tx];
    __syncthreads();
#pragma unroll
    for (int i = 0; i < 32; i += 8) {
        float v = tile[tx][ty + i];
        __nv_bfloat16 hb = __float2bfloat16(v);
        size_t o = (size_t)(tn + ty + i) * K + tk + tx;
        th[o] = hb;
        tl[o] = __float2bfloat16(v - __bfloat162float(hb));
    }
}

// ---------------- 3) 3-stage pipelined HMMA bf16-split GEMM ------------------
#define SPAD 40
template<int BM, int BN, int WM, int WN>
__global__ void __launch_bounds__(WM * WN * 32) k_hmma(
    const __nv_bfloat16* __restrict__ Ah, const __nv_bfloat16* __restrict__ Al,
    const __nv_bfloat16* __restrict__ Bh, const __nv_bfloat16* __restrict__ Bl,
    float* __restrict__ C, int N, int K)
{
    constexpr int T = WM * WN * 32;
    constexpr int ARR_A = BM * SPAD * 2;
    constexpr int ARR_BB = BN * SPAD * 2;
    constexpr int OFF_AH = 0;
    constexpr int OFF_AL = ARR_A;
    constexpr int OFF_BH = 2 * ARR_A;
    constexpr int OFF_BL = 2 * ARR_A + ARR_BB;
    constexpr int STAGE  = 2 * ARR_A + 2 * ARR_BB;

    extern __shared__ char dsm[];
    const uint32_t sb = smem_to_u32(dsm);
    const int tid = threadIdx.x, wid = tid >> 5, lane = tid & 31;
    const int m0 = blockIdx.x * BM, n0 = blockIdx.y * BN;
    const int wm = (wid % WM) * 32, wn = (wid / WM) * 32;

    float acc[2][4][4];
#pragma unroll
    for (int i = 0; i < 2; i++)
#pragma unroll
        for (int j = 0; j < 4; j++)
#pragma unroll
            for (int q = 0; q < 4; q++) acc[i][j][q] = 0.f;

    const int nch = K >> 5;

    auto issue = [&](int kc) {
        const uint32_t st = sb + (kc % 3) * STAGE;
#pragma unroll
        for (int idx = tid; idx < BM * 4; idx += T) {
            const int r = idx >> 2, c = idx & 3;
            const uint32_t so = (uint32_t)(r * SPAD + c * 8) * 2;
            const size_t gA = (size_t)(m0 + r) * K + kc * 32 + c * 8;
            cp16(st + OFF_AH + so, Ah + gA);
            cp16(st + OFF_AL + so, Al + gA);
        }
#pragma unroll
        for (int idx = tid; idx < BN * 4; idx += T) {
            const int r = idx >> 2, c = idx & 3;
            const uint32_t so = (uint32_t)(r * SPAD + c * 8) * 2;
            const size_t gB = (size_t)(n0 + r) * K + kc * 32 + c * 8;
            cp16(st + OFF_BH + so, Bh + gB);
            cp16(st + OFF_BL + so, Bl + gB);
        }
        CP_COMMIT();
    };

    issue(0);
    issue(1);

    for (int kc = 0; kc < nch; kc++) {
        if (kc + 1 < nch) { CP_WAIT(1); } else { CP_WAIT(0); }
        __syncthreads();
        if (kc + 2 < nch) issue(kc + 2);

        const uint32_t st = sb + (kc % 3) * STAGE;
#pragma unroll
        for (int ks = 0; ks < 2; ks++) {
            const int kb = ks * 16;
            const uint32_t aoff = ((wm + (lane & 15)) * SPAD + kb + 8 * (lane >> 4)) * 2;
            uint32_t afr[2][2][4];
            ldsm_x4(afr[0][0], st + OFF_AH + aoff);
            ldsm_x4(afr[0][1], st + OFF_AL + aoff);
            ldsm_x4(afr[1][0], st + OFF_AH + aoff + 16 * SPAD * 2);
            ldsm_x4(afr[1][1], st + OFF_AL + aoff + 16 * SPAD * 2);
            const uint32_t boff = ((wn + 8 * (lane >> 4) + (lane & 7)) * SPAD
                                   + kb + 8 * ((lane >> 3) & 1)) * 2;
            uint32_t bfr[2][2][4];
            ldsm_x4(bfr[0][0], st + OFF_BH + boff);
            ldsm_x4(bfr[0][1], st + OFF_BL + boff);
            ldsm_x4(bfr[1][0], st + OFF_BH + boff + 16 * SPAD * 2);
            ldsm_x4(bfr[1][1], st + OFF_BL + boff + 16 * SPAD * 2);

#pragma unroll
            for (int i = 0; i < 2; i++)
#pragma unroll
                for (int j = 0; j < 4; j++) {
                    const int p = j >> 1, s = (j & 1) * 2;
                    mma16816(acc[i][j], afr[i][0], bfr[p][0][s], bfr[p][0][s + 1]);
                    mma16816(acc[i][j], afr[i][0], bfr[p][1][s], bfr[p][1][s + 1]);
                    mma16816(acc[i][j], afr[i][1], bfr[p][0][s], bfr[p][0][s + 1]);
                }
        }
    }

    const int g = lane >> 2, t2 = (lane & 3) * 2;
#pragma unroll
    for (int i = 0; i < 2; i++)
#pragma unroll
        for (int j = 0; j < 4; j++) {
            const int rm = m0 + wm + 16 * i + g;
            const int cn = n0 + wn + 8 * j + t2;
            *(float2*)&C[(size_t)rm * N + cn]       = make_float2(acc[i][j][0], acc[i][j][1]);
            *(float2*)&C[(size_t)(rm + 8) * N + cn] = make_float2(acc[i][j][2], acc[i][j][3]);
        }
}

// ---------------- 4) warp-per-row SpMM: static-unrolled slots + prefetch ------
__global__ void __launch_bounds__(256) k_spmm(
    const float* __restrict__ y, const float* __restrict__ bias,
    __nv_bfloat16* __restrict__ oh, __nv_bfloat16* __restrict__ ol) {
    const int row = blockIdx.x * 8 + (threadIdx.x >> 5);
    const int lane = threadIdx.x & 31;
    const int cnt = g_cnt[row];
    const int base = row * CAP;

    float ev[8]; int ec[8];
#pragma unroll
    for (int s = 0; s < 8; s++) {
        int t = lane + s * 32;
        if (t < cnt) { ec[s] = g_ecol[base + t]; ev[s] = g_eval[base + t]; }
        else         { ec[s] = 0;               ev[s] = 0.f; }
    }

    float4 acc0 = make_float4(0.f, 0.f, 0.f, 0.f);
    float4 acc1 = make_float4(0.f, 0.f, 0.f, 0.f);
#pragma unroll
    for (int s = 0; s < 8; s++) {              // static s: ev/ec stay in regs
        if (s * 32 >= cnt) break;
        const int lim = min(32, cnt - s * 32);
        // depth-2 prefetch pipeline
        float wc = __shfl_sync(0xffffffffu, ev[s], 0);
        int   jc = __shfl_sync(0xffffffffu, ec[s], 0);
        const float4* yr = (const float4*)(y + (size_t)jc * DHID);
        float4 p0 = yr[lane], p1 = yr[lane + 32];
        for (int u = 1; u < lim; u++) {
            const float wn = __shfl_sync(0xffffffffu, ev[s], u);
            const int   jn = __shfl_sync(0xffffffffu, ec[s], u);
            const float4* yn = (const float4*)(y + (size_t)jn * DHID);
            float4 q0 = yn[lane], q1 = yn[lane + 32];
            acc0.x = fmaf(wc, p0.x, acc0.x); acc0.y = fmaf(wc, p0.y, acc0.y);
            acc0.z = fmaf(wc, p0.z, acc0.z); acc0.w = fmaf(wc, p0.w, acc0.w);
            acc1.x = fmaf(wc, p1.x, acc1.x); acc1.y = fmaf(wc, p1.y, acc1.y);
            acc1.z = fmaf(wc, p1.z, acc1.z); acc1.w = fmaf(wc, p1.w, acc1.w);
            wc = wn; p0 = q0; p1 = q1;
        }
        acc0.x = fmaf(wc, p0.x, acc0.x); acc0.y = fmaf(wc, p0.y, acc0.y);
        acc0.z = fmaf(wc, p0.z, acc0.z); acc0.w = fmaf(wc, p0.w, acc0.w);
        acc1.x = fmaf(wc, p1.x, acc1.x); acc1.y = fmaf(wc, p1.y, acc1.y);
        acc1.z = fmaf(wc, p1.z, acc1.z); acc1.w = fmaf(wc, p1.w, acc1.w);
    }
    const float4 b0 = ((const float4*)bias)[lane];
    const float4 b1 = ((const float4*)bias)[lane + 32];
    float r0[8] = { leaky(acc0.x + b0.x), leaky(acc0.y + b0.y),
                    leaky(acc0.z + b0.z), leaky(acc0.w + b0.w),
                    leaky(acc1.x + b1.x), leaky(acc1.y + b1.y),
                    leaky(acc1.z + b1.z), leaky(acc1.w + b1.w) };
    __nv_bfloat162 hv[4], lv[4];
#pragma unroll
    for (int q = 0; q < 4; q++) {
        int s0 = q * 2;
        __nv_bfloat16 ha = __float2bfloat16(r0[s0]), hb2 = __float2bfloat16(r0[s0 + 1]);
        hv[q] = __nv_bfloat162(ha, hb2);
        lv[q] = __nv_bfloat162(__float2bfloat16(r0[s0]     - __bfloat162float(ha)),
                               __float2bfloat16(r0[s0 + 1] - __bfloat162float(hb2)));
    }
    size_t o0 = (size_t)row * DHID + lane * 4;
    size_t o1 = (size_t)row * DHID + 128 + lane * 4;
    *(__nv_bfloat162*)(oh + o0)     = hv[0];
    *(__nv_bfloat162*)(oh + o0 + 2) = hv[1];
    *(__nv_bfloat162*)(oh + o1)     = hv[2];
    *(__nv_bfloat162*)(oh + o1 + 2) = hv[3];
    *(__nv_bfloat162*)(ol + o0)     = lv[0];
    *(__nv_bfloat162*)(ol + o0 + 2) = lv[1];
    *(__nv_bfloat162*)(ol + o1)     = lv[2];
    *(__nv_bfloat162*)(ol + o1 + 2) = lv[3];
}

// ---------------- 5) fused: f1/f2 per row + column partial sums ---------------
__global__ void k_feat(const float* __restrict__ h, const float* __restrict__ a) {
    __shared__ float sa1[DOUT], sa2[DOUT];
    const int b = blockIdx.x, tid = threadIdx.x;
    const int wid = tid >> 5, lane = tid & 31;
    if (tid < DOUT) { sa1[tid] = a[tid]; sa2[tid] = a[DOUT + tid]; }
    __syncthreads();

    const int r0 = b * 128;
#pragma unroll
    for (int rr = 0; rr < 16; rr++) {
        const int row = r0 + wid * 16 + rr;
        const float* hr = h + (size_t)row * DOUT;
        float s1 = 0.f, s2 = 0.f;
#pragma unroll
        for (int q = 0; q < 4; q++) {
            int c = lane + q * 32;
            float hv = hr[c];
            s1 = fmaf(hv, sa1[c], s1);
            s2 = fmaf(hv, sa2[c], s2);
        }
#pragma unroll
        for (int o = 16; o; o >>= 1) {
            s1 += __shfl_down_sync(0xffffffffu, s1, o);
            s2 += __shfl_down_sync(0xffffffffu, s2, o);
        }
        if (lane == 0) { g_f1[row] = s1; g_f2[row] = s2; }
    }

    if (tid < DOUT) {
        float s = 0.f;
        for (int r = 0; r < 128; r++) s += h[(size_t)(r0 + r) * DOUT + tid];
        g_part[b * DOUT + tid] = s;
    }
}
__global__ void k_mean() {
    const int c = threadIdx.x;
    float s = 0.f;
    for (int b = 0; b < 64; b++) s += g_part[b * DOUT + c];
    g_hmean[c] = s * (1.f / NN);
}

// ---------------- 6) warp-per-row softmax + h_prime: static slots + prefetch --
__global__ void __launch_bounds__(256) k_attn(const float* __restrict__ h,
                                              float* __restrict__ out) {
    const int row = blockIdx.x * 8 + (threadIdx.x >> 5);
    const int lane = threadIdx.x & 31;
    const int cnt = g_cnt[row];

    if (cnt == 0) {
        float4 v = ((const float4*)g_hmean)[lane];
        v.x = leaky(v.x); v.y = leaky(v.y); v.z = leaky(v.z); v.w = leaky(v.w);
        if (lane < 16) *(float4*)&out[(size_t)row * 64 + lane * 4] = v;
        else *(float4*)&out[(size_t)NN * 64 + (size_t)row * 64 + (lane - 16) * 4] = v;
        return;
    }

    const float f1i = g_f1[row];
    const int base = row * CAP;
    float ew[8]; int ec[8];
    float lmax = -INFINITY;
#pragma unroll
    for (int s = 0; s < 8; s++) {
        int t = lane + s * 32;
        if (t < cnt) {
            int j = g_ecol[base + t];
            float e = leaky(f1i + g_f2[j]);
            ec[s] = j; ew[s] = e;
            lmax = fmaxf(lmax, e);
        } else { ec[s] = 0; ew[s] = -INFINITY; }
    }
#pragma unroll
    for (int o = 16; o; o >>= 1) lmax = fmaxf(lmax, __shfl_xor_sync(0xffffffffu, lmax, o));

    float lsum = 0.f;
#pragma unroll
    for (int s = 0; s < 8; s++) {
        float w = (lane + s * 32 < cnt) ? __expf(ew[s] - lmax) : 0.f;
        ew[s] = w;
        lsum += w;
    }
#pragma unroll
    for (int o = 16; o; o >>= 1) lsum += __shfl_xor_sync(0xffffffffu, lsum, o);
    const float invZ = 1.f / lsum;

    float4 acc = make_float4(0.f, 0.f, 0.f, 0.f);
#pragma unroll
    for (int s = 0; s < 8; s++) {              // static s: ew/ec stay in regs
        if (s * 32 >= cnt) break;
        const int lim = min(32, cnt - s * 32);
        float wc = __shfl_sync(0xffffffffu, ew[s], 0);
        int   jc = __shfl_sync(0xffffffffu, ec[s], 0);
        float4 p = ((const float4*)(h + (size_t)jc * DOUT))[lane];
        for (int u = 1; u < lim; u++) {
            const float wn = __shfl_sync(0xffffffffu, ew[s], u);
            const int   jn = __shfl_sync(0xffffffffu, ec[s], u);
            float4 q = ((const float4*)(h + (size_t)jn * DOUT))[lane];
            acc.x = fmaf(wc, p.x, acc.x); acc.y = fmaf(wc, p.y, acc.y);
            acc.z = fmaf(wc, p.z, acc.z); acc.w = fmaf(wc, p.w, acc.w);
            wc = wn; p = q;
        }
        acc.x = fmaf(wc, p.x, acc.x); acc.y = fmaf(wc, p.y, acc.y);
        acc.z = fmaf(wc, p.z, acc.z); acc.w = fmaf(wc, p.w, acc.w);
    }
    float4 r = make_float4(leaky(acc.x * invZ), leaky(acc.y * invZ),
                           leaky(acc.z * invZ), leaky(acc.w * invZ));
    if (lane < 16) *(float4*)&out[(size_t)row * 64 + lane * 4] = r;
    else *(float4*)&out[(size_t)NN * 64 + (size_t)row * 64 + (lane - 16) * 4] = r;
}

// ---------------- launch -----------------------------------------------------
extern "C" void kernel_launch(void* const* d_in, const int* in_sizes, int n_in,
                              void* d_out, int out_size) {
    (void)in_sizes; (void)n_in; (void)out_size;
    const float* x   = (const float*)d_in[0];
    const float* adj = (const float*)d_in[1];
    const float* W1  = (const float*)d_in[2];
    const float* b1  = (const float*)d_in[3];
    const float* W2  = (const float*)d_in[4];
    const float* b2  = (const float*)d_in[5];
    const float* Wg  = (const float*)d_in[6];
    const float* a   = (const float*)d_in[7];
    float* out = (float*)d_out;

    void* p;
    cudaGetSymbolAddress(&p, g_y1);   float* y1 = (float*)p;
    cudaGetSymbolAddress(&p, g_y2);   float* y2 = (float*)p;
    cudaGetSymbolAddress(&p, g_h);    float* h  = (float*)p;
    cudaGetSymbolAddress(&p, g_xh);   __nv_bfloat16* xh  = (__nv_bfloat16*)p;
    cudaGetSymbolAddress(&p, g_xl);   __nv_bfloat16* xl  = (__nv_bfloat16*)p;
    cudaGetSymbolAddress(&p, g_x1h);  __nv_bfloat16* x1h = (__nv_bfloat16*)p;
    cudaGetSymbolAddress(&p, g_x1l);  __nv_bfloat16* x1l = (__nv_bfloat16*)p;
    cudaGetSymbolAddress(&p, g_x2h);  __nv_bfloat16* x2h = (__nv_bfloat16*)p;
    cudaGetSymbolAddress(&p, g_x2l);  __nv_bfloat16* x2l = (__nv_bfloat16*)p;
    cudaGetSymbolAddress(&p, g_w1th); __nv_bfloat16* w1th = (__nv_bfloat16*)p;
    cudaGetSymbolAddress(&p, g_w1tl); __nv_bfloat16* w1tl = (__nv_bfloat16*)p;
    cudaGetSymbolAddress(&p, g_w2th); __nv_bfloat16* w2th = (__nv_bfloat16*)p;
    cudaGetSymbolAddress(&p, g_w2tl); __nv_bfloat16* w2tl = (__nv_bfloat16*)p;
    cudaGetSymbolAddress(&p, g_wgth); __nv_bfloat16* wgth = (__nv_bfloat16*)p;
    cudaGetSymbolAddress(&p, g_wgtl); __nv_bfloat16* wgtl = (__nv_bfloat16*)p;

    constexpr int SMEM_BIG   = 3 * (2 * 128 * SPAD * 2 + 2 * 128 * SPAD * 2); // 122880
    constexpr int SMEM_SMALL = 3 * (2 * 64 * SPAD * 2 + 2 * 128 * SPAD * 2);  // 92160

    static cudaStream_t s2 = nullptr;
    static cudaEvent_t ev_fork = nullptr, ev_extract = nullptr;
    if (!s2) {
        cudaStreamCreateWithFlags(&s2, cudaStreamNonBlocking);
        cudaEventCreateWithFlags(&ev_fork, cudaEventDisableTiming);
        cudaEventCreateWithFlags(&ev_extract, cudaEventDisableTiming);
        cudaFuncSetAttribute(k_hmma<128, 128, 4, 4>, cudaFuncAttributeMaxDynamicSharedMemorySize, SMEM_BIG);
        cudaFuncSetAttribute(k_hmma<64, 128, 2, 4>,  cudaFuncAttributeMaxDynamicSharedMemorySize, SMEM_SMALL);
    }

    cudaEventRecord(ev_fork, 0);
    cudaStreamWaitEvent(s2, ev_fork, 0);
    k_extract<<<NN / 8, 256, 0, s2>>>(adj);       // zero-smem, co-resident
    cudaEventRecord(ev_extract, s2);

    k_prep<<<4320, 256>>>(x, W1, W2, Wg);
    k_hmma<128, 128, 4, 4><<<dim3(NN / 128, DHID / 128), 512, SMEM_BIG>>>(
        xh, xl, w1th, w1tl, y1, DHID, DIN);

    cudaStreamWaitEvent(0, ev_extract, 0);
    k_spmm<<<NN / 8, 256>>>(y1, b1, x1h, x1l);
    k_hmma<128, 128, 4, 4><<<dim3(NN / 128, DHID / 128), 512, SMEM_BIG>>>(
        x1h, x1l, w2th, w2tl, y2, DHID, DHID);
    k_spmm<<<NN / 8, 256>>>(y2, b2, x2h, x2l);
    k_hmma<64, 128, 2, 4><<<dim3(NN / 64, DOUT / 128), 256, SMEM_SMALL>>>(
        x2h, x2l, wgth, wgtl, h, DOUT, DHID);

    k_feat<<<64, 256>>>(h, a);
    k_mean<<<1, 128>>>();
    k_attn<<<NN / 8, 256>>>(h, out);
}

// round 17
// speedup vs baseline: 1.4063x; 1.0040x over previous
#include <cuda_runtime.h>
#include <cuda_bf16.h>
#include <math.h>
#include <stdint.h>

#define NN   8192
#define DIN  512
#define DHID 256
#define DOUT 128
#define CAP  256
#define NEG  0.25f

// ---------------- scratch (device globals) ----------------------------------
__device__ float g_y1[NN * DHID];
__device__ float g_y2[NN * DHID];
__device__ float g_h [NN * DOUT];
__device__ float g_f1[NN];
__device__ float g_f2[NN];
__device__ int   g_cnt [NN];
__device__ int   g_ecol[NN * CAP];
__device__ float g_eval[NN * CAP];
__device__ float g_part[64 * DOUT];
__device__ float g_hmean[DOUT];

__device__ __nv_bfloat16 g_xh [NN * DIN],  g_xl [NN * DIN];
__device__ __nv_bfloat16 g_x1h[NN * DHID], g_x1l[NN * DHID];
__device__ __nv_bfloat16 g_x2h[NN * DHID], g_x2l[NN * DHID];
__device__ __nv_bfloat16 g_w1th[DHID * DIN],  g_w1tl[DHID * DIN];
__device__ __nv_bfloat16 g_w2th[DHID * DHID], g_w2tl[DHID * DHID];
__device__ __nv_bfloat16 g_wgth[DOUT * DHID], g_wgtl[DOUT * DHID];

__device__ __forceinline__ float leaky(float x) { return x >= 0.f ? x : NEG * x; }

__device__ __forceinline__ uint32_t smem_to_u32(const void* p) {
    uint32_t a;
    asm("{ .reg .u64 t; cvta.to.shared.u64 t, %1; cvt.u32.u64 %0, t; }" : "=r"(a) : "l"(p));
    return a;
}
__device__ __forceinline__ void ldsm_x4(uint32_t* r, uint32_t addr) {
    asm volatile("ldmatrix.sync.aligned.m8n8.x4.shared.b16 {%0,%1,%2,%3}, [%4];"
                 : "=r"(r[0]), "=r"(r[1]), "=r"(r[2]), "=r"(r[3]) : "r"(addr));
}
__device__ __forceinline__ void mma16816(float* c, const uint32_t* a, uint32_t b0, uint32_t b1) {
    asm volatile("mma.sync.aligned.m16n8k16.row.col.f32.bf16.bf16.f32 "
                 "{%0,%1,%2,%3}, {%4,%5,%6,%7}, {%8,%9}, {%0,%1,%2,%3};"
                 : "+f"(c[0]), "+f"(c[1]), "+f"(c[2]), "+f"(c[3])
                 : "r"(a[0]), "r"(a[1]), "r"(a[2]), "r"(a[3]), "r"(b0), "r"(b1));
}
__device__ __forceinline__ void cp16(uint32_t saddr, const void* g) {
    asm volatile("cp.async.ca.shared.global [%0], [%1], 16;" :: "r"(saddr), "l"(g));
}
#define CP_COMMIT() asm volatile("cp.async.commit_group;" ::: "memory")
#define CP_WAIT(n)  asm volatile("cp.async.wait_group %0;" :: "n"(n) : "memory")

// ---------------- 1) edge extraction: warp-per-row, zero smem, MLP 8 ----------
__global__ void __launch_bounds__(256) k_extract(const float* __restrict__ adj) {
    const int row = blockIdx.x * 8 + (threadIdx.x >> 5);
    const int lane = threadIdx.x & 31;
    const float* arow = adj + (size_t)row * NN;
    const int base = row * CAP;
    const uint32_t below = (1u << lane) - 1u;

    int off = 0;
    for (int r = 0; r < 256; r += 8) {
        float v[8];
#pragma unroll
        for (int q = 0; q < 8; q++) v[q] = arow[(r + q) * 32 + lane];
#pragma unroll
        for (int q = 0; q < 8; q++) {
            uint32_t m = __ballot_sync(0xffffffffu, v[q] > 0.f);
            if (v[q] > 0.f) {
                int p = off + __popc(m & below);
                if (p < CAP) { g_ecol[base + p] = (r + q) * 32 + lane; g_eval[base + p] = v[q]; }
            }
            off += __popc(m);
        }
    }
    if (lane == 0) g_cnt[row] = off < CAP ? off : CAP;
}

// ---------------- 2) fused prep: x split + W transposes -----------------------
__global__ void k_prep(const float* __restrict__ x,
                       const float* __restrict__ W1, const float* __restrict__ W2,
                       const float* __restrict__ Wg) {
    int b = blockIdx.x;
    if (b < 4096) {
        int i = b * 256 + threadIdx.x;
        float4 v = ((const float4*)x)[i];
        __nv_bfloat16 h0 = __float2bfloat16(v.x), h1 = __float2bfloat16(v.y);
        __nv_bfloat16 h2 = __float2bfloat16(v.z), h3 = __float2bfloat16(v.w);
        __nv_bfloat162* hp = (__nv_bfloat162*)g_xh;
        __nv_bfloat162* lp = (__nv_bfloat162*)g_xl;
        hp[2 * i]     = __nv_bfloat162(h0, h1);
        hp[2 * i + 1] = __nv_bfloat162(h2, h3);
        lp[2 * i]     = __nv_bfloat162(__float2bfloat16(v.x - __bfloat162float(h0)),
                                       __float2bfloat16(v.y - __bfloat162float(h1)));
        lp[2 * i + 1] = __nv_bfloat162(__float2bfloat16(v.z - __bfloat162float(h2)),
                                       __float2bfloat16(v.w - __bfloat162float(h3)));
        return;
    }
    b -= 4096;
    __shared__ float tile[32][33];
    const float* W; __nv_bfloat16 *th, *tl; int K, N, tk, tn;
    if (b < 128) {
        W = W1; th = g_w1th; tl = g_w1tl; K = DIN; N = DHID;
        tk = (b >> 3) * 32; tn = (b & 7) * 32;
    } else if (b < 192) {
        b -= 128; W = W2; th = g_w2th; tl = g_w2tl; K = DHID; N = DHID;
        tk = (b >> 3) * 32; tn = (b & 7) * 32;
    } else {
        b -= 192; W = Wg; th = g_wgth; tl = g_wgtl; K = DHID; N = DOUT;
        tk = (b >> 2) * 32; tn = (b & 3) * 32;
    }
    const int tx = threadIdx.x & 31, ty = threadIdx.x >> 5;
#pragma unroll
    for (int i = 0; i < 32; i += 8)
        tile[ty + i][tx] = W[(size_t)(tk + ty + i) * N + tn + tx];
    __syncthreads();
#pragma unroll
    for (int i = 0; i < 32; i += 8) {
        float v = tile[tx][ty + i];
        __nv_bfloat16 hb = __float2bfloat16(v);
        size_t o = (size_t)(tn + ty + i) * K + tk + tx;
        th[o] = hb;
        tl[o] = __float2bfloat16(v - __bfloat162float(hb));
    }
}

// ---------------- 3) 3-stage pipelined HMMA bf16-split GEMM ------------------
#define SPAD 40
template<int BM, int BN, int WM, int WN>
__global__ void __launch_bounds__(WM * WN * 32) k_hmma(
    const __nv_bfloat16* __restrict__ Ah, const __nv_bfloat16* __restrict__ Al,
    const __nv_bfloat16* __restrict__ Bh, const __nv_bfloat16* __restrict__ Bl,
    float* __restrict__ C, int N, int K)
{
    constexpr int T = WM * WN * 32;
    constexpr int ARR_A = BM * SPAD * 2;
    constexpr int ARR_BB = BN * SPAD * 2;
    constexpr int OFF_AH = 0;
    constexpr int OFF_AL = ARR_A;
    constexpr int OFF_BH = 2 * ARR_A;
    constexpr int OFF_BL = 2 * ARR_A + ARR_BB;
    constexpr int STAGE  = 2 * ARR_A + 2 * ARR_BB;

    extern __shared__ char dsm[];
    const uint32_t sb = smem_to_u32(dsm);
    const int tid = threadIdx.x, wid = tid >> 5, lane = tid & 31;
    const int m0 = blockIdx.x * BM, n0 = blockIdx.y * BN;
    const int wm = (wid % WM) * 32, wn = (wid / WM) * 32;

    float acc[2][4][4];
#pragma unroll
    for (int i = 0; i < 2; i++)
#pragma unroll
        for (int j = 0; j < 4; j++)
#pragma unroll
            for (int q = 0; q < 4; q++) acc[i][j][q] = 0.f;

    const int nch = K >> 5;

    auto issue = [&](int kc) {
        const uint32_t st = sb + (kc % 3) * STAGE;
#pragma unroll
        for (int idx = tid; idx < BM * 4; idx += T) {
            const int r = idx >> 2, c = idx & 3;
            const uint32_t so = (uint32_t)(r * SPAD + c * 8) * 2;
            const size_t gA = (size_t)(m0 + r) * K + kc * 32 + c * 8;
            cp16(st + OFF_AH + so, Ah + gA);
            cp16(st + OFF_AL + so, Al + gA);
        }
#pragma unroll
        for (int idx = tid; idx < BN * 4; idx += T) {
            const int r = idx >> 2, c = idx & 3;
            const uint32_t so = (uint32_t)(r * SPAD + c * 8) * 2;
            const size_t gB = (size_t)(n0 + r) * K + kc * 32 + c * 8;
            cp16(st + OFF_BH + so, Bh + gB);
            cp16(st + OFF_BL + so, Bl + gB);
        }
        CP_COMMIT();
    };

    issue(0);
    issue(1);

    for (int kc = 0; kc < nch; kc++) {
        if (kc + 1 < nch) { CP_WAIT(1); } else { CP_WAIT(0); }
        __syncthreads();
        if (kc + 2 < nch) issue(kc + 2);

        const uint32_t st = sb + (kc % 3) * STAGE;
#pragma unroll
        for (int ks = 0; ks < 2; ks++) {
            const int kb = ks * 16;
            const uint32_t aoff = ((wm + (lane & 15)) * SPAD + kb + 8 * (lane >> 4)) * 2;
            uint32_t afr[2][2][4];
            ldsm_x4(afr[0][0], st + OFF_AH + aoff);
            ldsm_x4(afr[0][1], st + OFF_AL + aoff);
            ldsm_x4(afr[1][0], st + OFF_AH + aoff + 16 * SPAD * 2);
            ldsm_x4(afr[1][1], st + OFF_AL + aoff + 16 * SPAD * 2);
            const uint32_t boff = ((wn + 8 * (lane >> 4) + (lane & 7)) * SPAD
                                   + kb + 8 * ((lane >> 3) & 1)) * 2;
            uint32_t bfr[2][2][4];
            ldsm_x4(bfr[0][0], st + OFF_BH + boff);
            ldsm_x4(bfr[0][1], st + OFF_BL + boff);
            ldsm_x4(bfr[1][0], st + OFF_BH + boff + 16 * SPAD * 2);
            ldsm_x4(bfr[1][1], st + OFF_BL + boff + 16 * SPAD * 2);

#pragma unroll
            for (int i = 0; i < 2; i++)
#pragma unroll
                for (int j = 0; j < 4; j++) {
                    const int p = j >> 1, s = (j & 1) * 2;
                    mma16816(acc[i][j], afr[i][0], bfr[p][0][s], bfr[p][0][s + 1]);
                    mma16816(acc[i][j], afr[i][0], bfr[p][1][s], bfr[p][1][s + 1]);
                    mma16816(acc[i][j], afr[i][1], bfr[p][0][s], bfr[p][0][s + 1]);
                }
        }
    }

    const int g = lane >> 2, t2 = (lane & 3) * 2;
#pragma unroll
    for (int i = 0; i < 2; i++)
#pragma unroll
        for (int j = 0; j < 4; j++) {
            const int rm = m0 + wm + 16 * i + g;
            const int cn = n0 + wn + 8 * j + t2;
            *(float2*)&C[(size_t)rm * N + cn]       = make_float2(acc[i][j][0], acc[i][j][1]);
            *(float2*)&C[(size_t)(rm + 8) * N + cn] = make_float2(acc[i][j][2], acc[i][j][3]);
        }
}

// ---------------- 4) SpMM: 2 warps per row (half each), depth-2 prefetch ------
__global__ void __launch_bounds__(256) k_spmm(
    const float* __restrict__ y, const float* __restrict__ bias,
    __nv_bfloat16* __restrict__ oh, __nv_bfloat16* __restrict__ ol) {
    const int wid = threadIdx.x >> 5;
    const int row = blockIdx.x * 4 + (wid >> 1);
    const int half = wid & 1;
    const int lane = threadIdx.x & 31;
    const int cnt = g_cnt[row];
    const int base = row * CAP;
    const int col4 = lane + half * 32;          // float4 index within the row

    float ev[8]; int ec[8];
#pragma unroll
    for (int s = 0; s < 8; s++) {
        int t = lane + s * 32;
        if (t < cnt) { ec[s] = g_ecol[base + t]; ev[s] = g_eval[base + t]; }
        else         { ec[s] = 0;               ev[s] = 0.f; }
    }

    float4 acc = make_float4(0.f, 0.f, 0.f, 0.f);
#pragma unroll
    for (int s = 0; s < 8; s++) {
        if (s * 32 >= cnt) break;
        const int lim = min(32, cnt - s * 32);
        float wc = __shfl_sync(0xffffffffu, ev[s], 0);
        int   jc = __shfl_sync(0xffffffffu, ec[s], 0);
        float4 p = ((const float4*)(y + (size_t)jc * DHID))[col4];
        for (int u = 1; u < lim; u++) {
            const float wn = __shfl_sync(0xffffffffu, ev[s], u);
            const int   jn = __shfl_sync(0xffffffffu, ec[s], u);
            float4 q = ((const float4*)(y + (size_t)jn * DHID))[col4];
            acc.x = fmaf(wc, p.x, acc.x); acc.y = fmaf(wc, p.y, acc.y);
            acc.z = fmaf(wc, p.z, acc.z); acc.w = fmaf(wc, p.w, acc.w);
            wc = wn; p = q;
        }
        acc.x = fmaf(wc, p.x, acc.x); acc.y = fmaf(wc, p.y, acc.y);
        acc.z = fmaf(wc, p.z, acc.z); acc.w = fmaf(wc, p.w, acc.w);
    }
    const float4 bv = ((const float4*)bias)[col4];
    float r0 = leaky(acc.x + bv.x), r1 = leaky(acc.y + bv.y);
    float r2 = leaky(acc.z + bv.z), r3 = leaky(acc.w + bv.w);
    __nv_bfloat16 h0 = __float2bfloat16(r0), h1 = __float2bfloat16(r1);
    __nv_bfloat16 h2 = __float2bfloat16(r2), h3 = __float2bfloat16(r3);
    size_t o = (size_t)row * DHID + col4 * 4;
    *(__nv_bfloat162*)(oh + o)     = __nv_bfloat162(h0, h1);
    *(__nv_bfloat162*)(oh + o + 2) = __nv_bfloat162(h2, h3);
    *(__nv_bfloat162*)(ol + o)     = __nv_bfloat162(__float2bfloat16(r0 - __bfloat162float(h0)),
                                                    __float2bfloat16(r1 - __bfloat162float(h1)));
    *(__nv_bfloat162*)(ol + o + 2) = __nv_bfloat162(__float2bfloat16(r2 - __bfloat162float(h2)),
                                                    __float2bfloat16(r3 - __bfloat162float(h3)));
}

// ---------------- 5) fused: f1/f2 per row + column partial sums ---------------
__global__ void k_feat(const float* __restrict__ h, const float* __restrict__ a) {
    __shared__ float sa1[DOUT], sa2[DOUT];
    const int b = blockIdx.x, tid = threadIdx.x;
    const int wid = tid >> 5, lane = tid & 31;
    if (tid < DOUT) { sa1[tid] = a[tid]; sa2[tid] = a[DOUT + tid]; }
    __syncthreads();

    const int r0 = b * 128;
#pragma unroll
    for (int rr = 0; rr < 16; rr++) {
        const int row = r0 + wid * 16 + rr;
        const float* hr = h + (size_t)row * DOUT;
        float s1 = 0.f, s2 = 0.f;
#pragma unroll
        for (int q = 0; q < 4; q++) {
            int c = lane + q * 32;
            float hv = hr[c];
            s1 = fmaf(hv, sa1[c], s1);
            s2 = fmaf(hv, sa2[c], s2);
        }
#pragma unroll
        for (int o = 16; o; o >>= 1) {
            s1 += __shfl_down_sync(0xffffffffu, s1, o);
            s2 += __shfl_down_sync(0xffffffffu, s2, o);
        }
        if (lane == 0) { g_f1[row] = s1; g_f2[row] = s2; }
    }

    if (tid < DOUT) {
        float s = 0.f;
        for (int r = 0; r < 128; r++) s += h[(size_t)(r0 + r) * DOUT + tid];
        g_part[b * DOUT + tid] = s;
    }
}
__global__ void k_mean() {
    const int c = threadIdx.x;
    float s = 0.f;
    for (int b = 0; b < 64; b++) s += g_part[b * DOUT + c];
    g_hmean[c] = s * (1.f / NN);
}

// ---------------- 6) warp-per-row softmax + h_prime: depth-3 prefetch ---------
__global__ void __launch_bounds__(256) k_attn(const float* __restrict__ h,
                                              float* __restrict__ out) {
    const int row = blockIdx.x * 8 + (threadIdx.x >> 5);
    const int lane = threadIdx.x & 31;
    const int cnt = g_cnt[row];

    if (cnt == 0) {
        float4 v = ((const float4*)g_hmean)[lane];
        v.x = leaky(v.x); v.y = leaky(v.y); v.z = leaky(v.z); v.w = leaky(v.w);
        if (lane < 16) *(float4*)&out[(size_t)row * 64 + lane * 4] = v;
        else *(float4*)&out[(size_t)NN * 64 + (size_t)row * 64 + (lane - 16) * 4] = v;
        return;
    }

    const float f1i = g_f1[row];
    const int base = row * CAP;
    float ew[8]; int ec[8];
    float lmax = -INFINITY;
#pragma unroll
    for (int s = 0; s < 8; s++) {
        int t = lane + s * 32;
        if (t < cnt) {
            int j = g_ecol[base + t];
            float e = leaky(f1i + g_f2[j]);
            ec[s] = j; ew[s] = e;
            lmax = fmaxf(lmax, e);
        } else { ec[s] = 0; ew[s] = -INFINITY; }
    }
#pragma unroll
    for (int o = 16; o; o >>= 1) lmax = fmaxf(lmax, __shfl_xor_sync(0xffffffffu, lmax, o));

    float lsum = 0.f;
#pragma unroll
    for (int s = 0; s < 8; s++) {
        float w = (lane + s * 32 < cnt) ? __expf(ew[s] - lmax) : 0.f;
        ew[s] = w;
        lsum += w;
    }
#pragma unroll
    for (int o = 16; o; o >>= 1) lsum += __shfl_xor_sync(0xffffffffu, lsum, o);
    const float invZ = 1.f / lsum;

    float4 acc = make_float4(0.f, 0.f, 0.f, 0.f);
#pragma unroll
    for (int s = 0; s < 8; s++) {
        if (s * 32 >= cnt) break;
        const int lim = min(32, cnt - s * 32);
        // depth-3: two future edges in flight
        float w0 = __shfl_sync(0xffffffffu, ew[s], 0);
        int   j0 = __shfl_sync(0xffffffffu, ec[s], 0);
        float4 p0 = ((const float4*)(h + (size_t)j0 * DOUT))[lane];
        if (lim == 1) {
            acc.x = fmaf(w0, p0.x, acc.x); acc.y = fmaf(w0, p0.y, acc.y);
            acc.z = fmaf(w0, p0.z, acc.z); acc.w = fmaf(w0, p0.w, acc.w);
            continue;
        }
        float w1 = __shfl_sync(0xffffffffu, ew[s], 1);
        int   j1 = __shfl_sync(0xffffffffu, ec[s], 1);
        float4 p1 = ((const float4*)(h + (size_t)j1 * DOUT))[lane];
        for (int u = 2; u < lim; u++) {
            const float w2 = __shfl_sync(0xffffffffu, ew[s], u);
            const int   j2 = __shfl_sync(0xffffffffu, ec[s], u);
            float4 p2 = ((const float4*)(h + (size_t)j2 * DOUT))[lane];
            acc.x = fmaf(w0, p0.x, acc.x); acc.y = fmaf(w0, p0.y, acc.y);
            acc.z = fmaf(w0, p0.z, acc.z); acc.w = fmaf(w0, p0.w, acc.w);
            w0 = w1; p0 = p1; w1 = w2; p1 = p2;
        }
        acc.x = fmaf(w0, p0.x, acc.x); acc.y = fmaf(w0, p0.y, acc.y);
        acc.z = fmaf(w0, p0.z, acc.z); acc.w = fmaf(w0, p0.w, acc.w);
        acc.x = fmaf(w1, p1.x, acc.x); acc.y = fmaf(w1, p1.y, acc.y);
        acc.z = fmaf(w1, p1.z, acc.z); acc.w = fmaf(w1, p1.w, acc.w);
    }
    float4 r = make_float4(leaky(acc.x * invZ), leaky(acc.y * invZ),
                           leaky(acc.z * invZ), leaky(acc.w * invZ));
    if (lane < 16) *(float4*)&out[(size_t)row * 64 + lane * 4] = r;
    else *(float4*)&out[(size_t)NN * 64 + (size_t)row * 64 + (lane - 16) * 4] = r;
}

// ---------------- launch -----------------------------------------------------
extern "C" void kernel_launch(void* const* d_in, const int* in_sizes, int n_in,
                              void* d_out, int out_size) {
    (void)in_sizes; (void)n_in; (void)out_size;
    const float* x   = (const float*)d_in[0];
    const float* adj = (const float*)d_in[1];
    const float* W1  = (const float*)d_in[2];
    const float* b1  = (const float*)d_in[3];
    const float* W2  = (const float*)d_in[4];
    const float* b2  = (const float*)d_in[5];
    const float* Wg  = (const float*)d_in[6];
    const float* a   = (const float*)d_in[7];
    float* out = (float*)d_out;

    void* p;
    cudaGetSymbolAddress(&p, g_y1);   float* y1 = (float*)p;
    cudaGetSymbolAddress(&p, g_y2);   float* y2 = (float*)p;
    cudaGetSymbolAddress(&p, g_h);    float* h  = (float*)p;
    cudaGetSymbolAddress(&p, g_xh);   __nv_bfloat16* xh  = (__nv_bfloat16*)p;
    cudaGetSymbolAddress(&p, g_xl);   __nv_bfloat16* xl  = (__nv_bfloat16*)p;
    cudaGetSymbolAddress(&p, g_x1h);  __nv_bfloat16* x1h = (__nv_bfloat16*)p;
    cudaGetSymbolAddress(&p, g_x1l);  __nv_bfloat16* x1l = (__nv_bfloat16*)p;
    cudaGetSymbolAddress(&p, g_x2h);  __nv_bfloat16* x2h = (__nv_bfloat16*)p;
    cudaGetSymbolAddress(&p, g_x2l);  __nv_bfloat16* x2l = (__nv_bfloat16*)p;
    cudaGetSymbolAddress(&p, g_w1th); __nv_bfloat16* w1th = (__nv_bfloat16*)p;
    cudaGetSymbolAddress(&p, g_w1tl); __nv_bfloat16* w1tl = (__nv_bfloat16*)p;
    cudaGetSymbolAddress(&p, g_w2th); __nv_bfloat16* w2th = (__nv_bfloat16*)p;
    cudaGetSymbolAddress(&p, g_w2tl); __nv_bfloat16* w2tl = (__nv_bfloat16*)p;
    cudaGetSymbolAddress(&p, g_wgth); __nv_bfloat16* wgth = (__nv_bfloat16*)p;
    cudaGetSymbolAddress(&p, g_wgtl); __nv_bfloat16* wgtl = (__nv_bfloat16*)p;

    constexpr int SMEM_BIG   = 3 * (2 * 128 * SPAD * 2 + 2 * 128 * SPAD * 2); // 122880
    constexpr int SMEM_SMALL = 3 * (2 * 64 * SPAD * 2 + 2 * 128 * SPAD * 2);  // 92160

    static cudaStream_t s2 = nullptr;
    static cudaEvent_t ev_fork = nullptr, ev_extract = nullptr;
    if (!s2) {
        cudaStreamCreateWithFlags(&s2, cudaStreamNonBlocking);
        cudaEventCreateWithFlags(&ev_fork, cudaEventDisableTiming);
        cudaEventCreateWithFlags(&ev_extract, cudaEventDisableTiming);
        cudaFuncSetAttribute(k_hmma<128, 128, 4, 4>, cudaFuncAttributeMaxDynamicSharedMemorySize, SMEM_BIG);
        cudaFuncSetAttribute(k_hmma<64, 128, 2, 4>,  cudaFuncAttributeMaxDynamicSharedMemorySize, SMEM_SMALL);
    }

    cudaEventRecord(ev_fork, 0);
    cudaStreamWaitEvent(s2, ev_fork, 0);
    k_extract<<<NN / 8, 256, 0, s2>>>(adj);       // zero-smem, co-resident
    cudaEventRecord(ev_extract, s2);

    k_prep<<<4320, 256>>>(x, W1, W2, Wg);
    k_hmma<128, 128, 4, 4><<<dim3(NN / 128, DHID / 128), 512, SMEM_BIG>>>(
        xh, xl, w1th, w1tl, y1, DHID, DIN);

    cudaStreamWaitEvent(0, ev_extract, 0);
    k_spmm<<<NN / 4, 256>>>(y1, b1, x1h, x1l);
    k_hmma<128, 128, 4, 4><<<dim3(NN / 128, DHID / 128), 512, SMEM_BIG>>>(
        x1h, x1l, w2th, w2tl, y2, DHID, DHID);
    k_spmm<<<NN / 4, 256>>>(y2, b2, x2h, x2l);
    k_hmma<64, 128, 2, 4><<<dim3(NN / 64, DOUT / 128), 256, SMEM_SMALL>>>(
        x2h, x2l, wgth, wgtl, h, DOUT, DHID);

    k_feat<<<64, 256>>>(h, a);
    k_mean<<<1, 128>>>();
    k_attn<<<NN / 8, 256>>>(h, out);
}